// round 1
// baseline (speedup 1.0000x reference)
#include <cuda_runtime.h>
#include <cuda_bf16.h>
#include <math.h>

// Problem constants
#define DIM      1024
#define D_INNER  2048
#define D_STATE  16
#define D_CONV   4
#define DT_RANK  64
#define B_SZ     2
#define T_LEN    2048
#define ROWS     (B_SZ * T_LEN)       // 4096
#define PROJ_N   (DT_RANK + 2 * D_STATE)  // 96

// Output offsets (floats): out | h_final | new_conv_state
#define OFF_H    (ROWS * DIM)                         // 4194304
#define OFF_CONV (OFF_H + B_SZ * D_INNER * D_STATE)   // 4259840

// Scratch buffers (device globals; allocation-free per harness rules)
__device__ float g_xz[(size_t)ROWS * (2 * D_INNER)];   // [4096][4096]: x_in | z
__device__ float g_xconv[(size_t)ROWS * D_INNER];      // [4096][2048]
__device__ float g_proj[(size_t)ROWS * PROJ_N];        // [4096][96]
__device__ float g_dt[(size_t)ROWS * D_INNER];         // [4096][2048]
__device__ float g_y[(size_t)ROWS * D_INNER];          // [4096][2048]

// ---------------------------------------------------------------------------
// Generic fp32 GEMM: C[M,N] = A[M,K(lda)] * B[K,N(ldb)]  (+optional epilogue)
// 128x128 block, BK=16, 256 threads, 8x8 per-thread microtile.
// epi==1: v += bias[col]; v = softplus(v)
// ---------------------------------------------------------------------------
__global__ void gemm128(const float* __restrict__ A, int lda,
                        const float* __restrict__ B, int ldb,
                        float* __restrict__ C, int ldc,
                        int M, int N, int K,
                        const float* __restrict__ bias, int epi)
{
    __shared__ float As[16][132];   // padded to keep float4 alignment, reduce conflicts
    __shared__ float Bs[16][128];

    const int tid = threadIdx.x;
    const int tx = tid & 15;        // 0..15 -> column group
    const int ty = tid >> 4;        // 0..15 -> row group
    const int blockRow = blockIdx.y * 128;
    const int blockCol = blockIdx.x * 128;

    float acc[8][8];
#pragma unroll
    for (int i = 0; i < 8; i++)
#pragma unroll
        for (int j = 0; j < 8; j++) acc[i][j] = 0.f;

    for (int k0 = 0; k0 < K; k0 += 16) {
        // Load A tile (128 rows x 16 k), coalesced along k
#pragma unroll
        for (int i = 0; i < 8; i++) {
            int e = tid + i * 256;
            int k = e & 15, m = e >> 4;
            int gr = blockRow + m, gc = k0 + k;
            As[k][m] = (gr < M && gc < K) ? A[(size_t)gr * lda + gc] : 0.f;
        }
        // Load B tile (16 k x 128 cols), coalesced along n
#pragma unroll
        for (int i = 0; i < 8; i++) {
            int e = tid + i * 256;
            int n = e & 127, k = e >> 7;
            int gr = k0 + k, gc = blockCol + n;
            Bs[k][n] = (gr < K && gc < N) ? B[(size_t)gr * ldb + gc] : 0.f;
        }
        __syncthreads();

#pragma unroll
        for (int kk = 0; kk < 16; kk++) {
            float a[8], b[8];
#pragma unroll
            for (int i = 0; i < 8; i++) a[i] = As[kk][ty * 8 + i];
#pragma unroll
            for (int j = 0; j < 8; j++) b[j] = Bs[kk][tx * 8 + j];
#pragma unroll
            for (int i = 0; i < 8; i++)
#pragma unroll
                for (int j = 0; j < 8; j++)
                    acc[i][j] = fmaf(a[i], b[j], acc[i][j]);
        }
        __syncthreads();
    }

#pragma unroll
    for (int i = 0; i < 8; i++) {
        int row = blockRow + ty * 8 + i;
        if (row >= M) continue;
#pragma unroll
        for (int j = 0; j < 8; j++) {
            int col = blockCol + tx * 8 + j;
            if (col >= N) continue;
            float v = acc[i][j];
            if (epi == 1) {
                v += bias[col];
                // softplus, numerically stable
                v = (v > 20.f) ? v : log1pf(__expf(v));
            }
            C[(size_t)row * ldc + col] = v;
        }
    }
}

// ---------------------------------------------------------------------------
// Depthwise causal conv (D_CONV=4) + bias + SiLU.
// x_in lives in g_xz[:, :D_INNER]. Output -> g_xconv [b*T+t][d].
// ---------------------------------------------------------------------------
__global__ void conv_kernel(const float* __restrict__ conv_state,
                            const float* __restrict__ conv_w,
                            const float* __restrict__ conv_b)
{
    int d = blockIdx.x * 256 + threadIdx.x;   // 0..2047
    int t = blockIdx.y;                       // 0..2047
    int b = blockIdx.z;                       // 0..1

    float acc = conv_b[d];
#pragma unroll
    for (int k = 0; k < D_CONV; k++) {
        int i = t + k;   // padded index; pad length = 3
        float v;
        if (i < D_CONV - 1)
            v = conv_state[((size_t)b * D_INNER + d) * (D_CONV - 1) + i];
        else
            v = g_xz[((size_t)b * T_LEN + (i - (D_CONV - 1))) * (2 * D_INNER) + d];
        acc = fmaf(conv_w[d * D_CONV + k], v, acc);
    }
    float sig = 1.f / (1.f + __expf(-acc));
    g_xconv[((size_t)b * T_LEN + t) * D_INNER + d] = acc * sig;
}

// new_conv_state[b][d][j] = x_in[b][T-3+j][d]  -> d_out at OFF_CONV
__global__ void convstate_kernel(float* __restrict__ outp)
{
    int idx = blockIdx.x * 256 + threadIdx.x;
    if (idx >= B_SZ * D_INNER * (D_CONV - 1)) return;
    int j = idx % (D_CONV - 1);
    int d = (idx / (D_CONV - 1)) % D_INNER;
    int b = idx / (D_INNER * (D_CONV - 1));
    outp[idx] = g_xz[((size_t)b * T_LEN + (T_LEN - (D_CONV - 1) + j)) * (2 * D_INNER) + d];
}

// ---------------------------------------------------------------------------
// Sequential selective scan over T. One thread per (b,d); 16 states in regs.
// Fuses y = (h.C + D*x) * silu(z). Writes g_y and h_final.
// blockDim = 128 threads (128 consecutive d of one b). grid (16, B).
// ---------------------------------------------------------------------------
__global__ void scan_kernel(const float* __restrict__ ssm0,
                            const float* __restrict__ A_log,
                            const float* __restrict__ D_skip,
                            float* __restrict__ h_out)
{
    int d = blockIdx.x * 128 + threadIdx.x;   // 0..2047
    int b = blockIdx.y;

    float h[D_STATE], A[D_STATE];
#pragma unroll
    for (int n = 0; n < D_STATE; n++) {
        h[n] = ssm0[((size_t)b * D_INNER + d) * D_STATE + n];
        A[n] = -__expf(A_log[d * D_STATE + n]);
    }
    const float dsk = D_skip[d];

    __shared__ float sBC[2 * D_STATE];   // B_t then C_t

    for (int t = 0; t < T_LEN; t++) {
        size_t row = (size_t)b * T_LEN + t;
        if (threadIdx.x < 2 * D_STATE)
            sBC[threadIdx.x] = g_proj[row * PROJ_N + DT_RANK + threadIdx.x];
        __syncthreads();

        float dt = g_dt[row * D_INNER + d];
        float xc = g_xconv[row * D_INNER + d];

        float y = 0.f;
#pragma unroll
        for (int n = 0; n < D_STATE; n++) {
            float dA = __expf(dt * A[n]);
            h[n] = fmaf(dA, h[n], dt * sBC[n] * xc);
            y = fmaf(h[n], sBC[D_STATE + n], y);
        }
        y = fmaf(dsk, xc, y);

        float z = g_xz[row * (2 * D_INNER) + D_INNER + d];
        float sz = z / (1.f + __expf(-z));
        g_y[row * D_INNER + d] = y * sz;
        __syncthreads();
    }

#pragma unroll
    for (int n = 0; n < D_STATE; n++)
        h_out[((size_t)b * D_INNER + d) * D_STATE + n] = h[n];
}

// ---------------------------------------------------------------------------
extern "C" void kernel_launch(void* const* d_in, const int* in_sizes, int n_in,
                              void* d_out, int out_size)
{
    const float* x          = (const float*)d_in[0];
    const float* ssm_state  = (const float*)d_in[1];
    const float* conv_state = (const float*)d_in[2];
    const float* w_in       = (const float*)d_in[3];
    const float* conv_w     = (const float*)d_in[4];
    const float* conv_b     = (const float*)d_in[5];
    const float* w_x        = (const float*)d_in[6];
    const float* w_dt       = (const float*)d_in[7];
    const float* b_dt       = (const float*)d_in[8];
    const float* A_log      = (const float*)d_in[9];
    const float* D_skip     = (const float*)d_in[10];
    const float* w_out      = (const float*)d_in[11];
    float* out = (float*)d_out;

    float *xz, *xconv, *proj, *dt, *y;
    cudaGetSymbolAddress((void**)&xz,    g_xz);
    cudaGetSymbolAddress((void**)&xconv, g_xconv);
    cudaGetSymbolAddress((void**)&proj,  g_proj);
    cudaGetSymbolAddress((void**)&dt,    g_dt);
    cudaGetSymbolAddress((void**)&y,     g_y);

    // 1) xz = x @ w_in   (4096 x 1024) @ (1024 x 4096)
    gemm128<<<dim3(4096 / 128, 4096 / 128), 256>>>(
        x, DIM, w_in, 2 * D_INNER, xz, 2 * D_INNER,
        ROWS, 2 * D_INNER, DIM, nullptr, 0);

    // 2) depthwise conv + silu
    conv_kernel<<<dim3(D_INNER / 256, T_LEN, B_SZ), 256>>>(conv_state, conv_w, conv_b);

    // new conv state output
    convstate_kernel<<<(B_SZ * D_INNER * (D_CONV - 1) + 255) / 256, 256>>>(out + OFF_CONV);

    // 3) proj = x_conv @ w_x   (4096 x 2048) @ (2048 x 96)
    gemm128<<<dim3(1, ROWS / 128), 256>>>(
        xconv, D_INNER, w_x, PROJ_N, proj, PROJ_N,
        ROWS, PROJ_N, D_INNER, nullptr, 0);

    // 4) dt = softplus(proj[:, :64] @ w_dt + b_dt)   (4096 x 64) @ (64 x 2048)
    gemm128<<<dim3(D_INNER / 128, ROWS / 128), 256>>>(
        proj, PROJ_N, w_dt, D_INNER, dt, D_INNER,
        ROWS, D_INNER, DT_RANK, b_dt, 1);

    // 5) selective scan (writes g_y and h_final)
    scan_kernel<<<dim3(D_INNER / 128, B_SZ), 128>>>(ssm_state, A_log, D_skip, out + OFF_H);

    // 6) out = y_gated @ w_out   (4096 x 2048) @ (2048 x 1024)
    gemm128<<<dim3(DIM / 128, ROWS / 128), 256>>>(
        y, D_INNER, w_out, DIM, out, DIM,
        ROWS, DIM, D_INNER, nullptr, 0);
}

// round 2
// speedup vs baseline: 1.8098x; 1.8098x over previous
#include <cuda_runtime.h>
#include <cuda_bf16.h>
#include <math.h>

// Problem constants
#define DIM      1024
#define D_INNER  2048
#define D_STATE  16
#define D_CONV   4
#define DT_RANK  64
#define B_SZ     2
#define T_LEN    2048
#define ROWS     (B_SZ * T_LEN)           // 4096
#define PROJ_N   (DT_RANK + 2 * D_STATE)  // 96
#define KSPLIT   8

// Output offsets (floats): out | h_final | new_conv_state
#define OFF_H    (ROWS * DIM)                         // 4194304
#define OFF_CONV (OFF_H + B_SZ * D_INNER * D_STATE)   // 4259840

// Scratch (device globals)
__device__ float g_xz[(size_t)ROWS * (2 * D_INNER)];           // x_in | z
__device__ float g_xconv[(size_t)ROWS * D_INNER];
__device__ float g_projp[(size_t)KSPLIT * ROWS * PROJ_N];      // split-K partials
__device__ float g_proj[(size_t)ROWS * PROJ_N];
__device__ float g_dt[(size_t)ROWS * D_INNER];
__device__ float g_y[(size_t)ROWS * D_INNER];

// ----- packed f32x2 helpers -------------------------------------------------
__device__ __forceinline__ unsigned long long pack2(float a, float b) {
    unsigned long long r;
    asm("mov.b64 %0, {%1, %2};" : "=l"(r) : "f"(a), "f"(b));
    return r;
}
__device__ __forceinline__ void unpack2(unsigned long long v, float& a, float& b) {
    asm("mov.b64 {%0, %1}, %2;" : "=f"(a), "=f"(b) : "l"(v));
}
#define FMA2(d, a, b) asm("fma.rn.f32x2 %0, %1, %2, %0;" : "+l"(d) : "l"(a), "l"(b))

// ----------------------------------------------------------------------------
// fp32x2 GEMM: C[M,N] = A[M,K] * B[K,N]. 128x128 tile, BK=16, 256 threads,
// 8x8 microtile as 8x4 f32x2 pairs, double-buffered smem, float4 gmem loads.
// mode 0: plain store. mode 1: +bias[col], softplus.
// Split-K via gridDim.z: each z-slice handles kLen Ks starting at z*kLen and
// writes to C + z*zStride (deterministic partials).
// Requirements: M multiple of 128 (full rows), K-chunk multiple of 16,
// lda/ldb/ldc/N multiples of 4.
// ----------------------------------------------------------------------------
__global__ void __launch_bounds__(256) gemm_f2(
    const float* __restrict__ A, int lda,
    const float* __restrict__ B, int ldb,
    float* __restrict__ C, int ldc,
    int N, int kLen, size_t zStride,
    const float* __restrict__ bias, int mode)
{
    __shared__ float As[2][16][132];
    __shared__ float Bs[2][16][128];

    const int tid = threadIdx.x;
    const int tx = tid & 15;
    const int ty = tid >> 4;
    const int bRow = blockIdx.y * 128;
    const int bCol = blockIdx.x * 128;
    const int kBase = blockIdx.z * kLen;

    // A loader: elems e=tid, tid+256 of 512; row=e>>2, kq=(e&3)*4
    const int ar0 = tid >> 2;            // 0..63
    const int ar1 = ar0 + 64;            // 64..127
    const int aq  = (tid & 3) * 4;       // 0,4,8,12
    // B loader: kr = tid>>5 (0..7 and +8), n = (tid&31)*4
    const int bk0 = tid >> 5;
    const int bk1 = bk0 + 8;
    const int bn  = (tid & 31) * 4;

    const float* Ab = A + (size_t)bRow * lda + kBase;
    const float* Bb = B + (size_t)kBase * ldb + bCol;
    const bool bok = (bCol + bn) < N;    // N % 4 == 0 so whole float4 in/out

    unsigned long long acc[8][4];
#pragma unroll
    for (int i = 0; i < 8; i++)
#pragma unroll
        for (int j = 0; j < 4; j++) acc[i][j] = 0ull;

    float4 pa0, pa1, pb0, pb1;
    const float4 f4z = make_float4(0.f, 0.f, 0.f, 0.f);

    // stage 0 load
    pa0 = *(const float4*)(Ab + (size_t)ar0 * lda + aq);
    pa1 = *(const float4*)(Ab + (size_t)ar1 * lda + aq);
    pb0 = bok ? *(const float4*)(Bb + (size_t)bk0 * ldb + bn) : f4z;
    pb1 = bok ? *(const float4*)(Bb + (size_t)bk1 * ldb + bn) : f4z;
    {
        As[0][aq + 0][ar0] = pa0.x; As[0][aq + 1][ar0] = pa0.y;
        As[0][aq + 2][ar0] = pa0.z; As[0][aq + 3][ar0] = pa0.w;
        As[0][aq + 0][ar1] = pa1.x; As[0][aq + 1][ar1] = pa1.y;
        As[0][aq + 2][ar1] = pa1.z; As[0][aq + 3][ar1] = pa1.w;
        *(float4*)&Bs[0][bk0][bn] = pb0;
        *(float4*)&Bs[0][bk1][bn] = pb1;
    }
    __syncthreads();

    const int nk = kLen / 16;
    for (int ik = 0; ik < nk; ik++) {
        const int cur = ik & 1;
        const bool pf = (ik + 1) < nk;
        if (pf) {
            const int kb = 16 * (ik + 1);
            pa0 = *(const float4*)(Ab + (size_t)ar0 * lda + kb + aq);
            pa1 = *(const float4*)(Ab + (size_t)ar1 * lda + kb + aq);
            pb0 = bok ? *(const float4*)(Bb + (size_t)(kb + bk0) * ldb + bn) : f4z;
            pb1 = bok ? *(const float4*)(Bb + (size_t)(kb + bk1) * ldb + bn) : f4z;
        }
#pragma unroll
        for (int kk = 0; kk < 16; kk++) {
            const float* as = &As[cur][kk][ty * 8];
            float4 av0 = *(const float4*)as;
            float4 av1 = *(const float4*)(as + 4);
            const unsigned long long* bs = (const unsigned long long*)&Bs[cur][kk][tx * 8];
            unsigned long long bp0 = bs[0], bp1 = bs[1], bp2 = bs[2], bp3 = bs[3];

            unsigned long long a2[8];
            a2[0] = pack2(av0.x, av0.x); a2[1] = pack2(av0.y, av0.y);
            a2[2] = pack2(av0.z, av0.z); a2[3] = pack2(av0.w, av0.w);
            a2[4] = pack2(av1.x, av1.x); a2[5] = pack2(av1.y, av1.y);
            a2[6] = pack2(av1.z, av1.z); a2[7] = pack2(av1.w, av1.w);
#pragma unroll
            for (int i = 0; i < 8; i++) {
                FMA2(acc[i][0], a2[i], bp0);
                FMA2(acc[i][1], a2[i], bp1);
                FMA2(acc[i][2], a2[i], bp2);
                FMA2(acc[i][3], a2[i], bp3);
            }
        }
        if (pf) {
            const int nxt = cur ^ 1;
            As[nxt][aq + 0][ar0] = pa0.x; As[nxt][aq + 1][ar0] = pa0.y;
            As[nxt][aq + 2][ar0] = pa0.z; As[nxt][aq + 3][ar0] = pa0.w;
            As[nxt][aq + 0][ar1] = pa1.x; As[nxt][aq + 1][ar1] = pa1.y;
            As[nxt][aq + 2][ar1] = pa1.z; As[nxt][aq + 3][ar1] = pa1.w;
            *(float4*)&Bs[nxt][bk0][bn] = pb0;
            *(float4*)&Bs[nxt][bk1][bn] = pb1;
            __syncthreads();
        }
    }

    // epilogue
    float* Cz = C + (size_t)blockIdx.z * zStride;
#pragma unroll
    for (int i = 0; i < 8; i++) {
        const int row = bRow + ty * 8 + i;
        float v[8];
#pragma unroll
        for (int j = 0; j < 4; j++) unpack2(acc[i][j], v[2 * j], v[2 * j + 1]);
#pragma unroll
        for (int j = 0; j < 8; j++) {
            const int col = bCol + tx * 8 + j;
            if (col < N) {
                float x = v[j];
                if (mode == 1) {
                    x += bias[col];
                    x = (x > 20.f) ? x : log1pf(__expf(x));
                }
                Cz[(size_t)row * ldc + col] = x;
            }
        }
    }
}

// reduce split-K partials of proj
__global__ void reduce_proj()
{
    int i = blockIdx.x * 256 + threadIdx.x;
    if (i >= ROWS * PROJ_N) return;
    float s = 0.f;
#pragma unroll
    for (int p = 0; p < KSPLIT; p++) s += g_projp[(size_t)p * ROWS * PROJ_N + i];
    g_proj[i] = s;
}

// ----------------------------------------------------------------------------
// Depthwise causal conv (D_CONV=4) + bias + SiLU.
// ----------------------------------------------------------------------------
__global__ void conv_kernel(const float* __restrict__ conv_state,
                            const float* __restrict__ conv_w,
                            const float* __restrict__ conv_b)
{
    int d = blockIdx.x * 256 + threadIdx.x;
    int t = blockIdx.y;
    int b = blockIdx.z;

    float acc = conv_b[d];
#pragma unroll
    for (int k = 0; k < D_CONV; k++) {
        int i = t + k;
        float v;
        if (i < D_CONV - 1)
            v = conv_state[((size_t)b * D_INNER + d) * (D_CONV - 1) + i];
        else
            v = g_xz[((size_t)b * T_LEN + (i - (D_CONV - 1))) * (2 * D_INNER) + d];
        acc = fmaf(conv_w[d * D_CONV + k], v, acc);
    }
    float sig = 1.f / (1.f + __expf(-acc));
    g_xconv[((size_t)b * T_LEN + t) * D_INNER + d] = acc * sig;
}

__global__ void convstate_kernel(float* __restrict__ outp)
{
    int idx = blockIdx.x * 256 + threadIdx.x;
    if (idx >= B_SZ * D_INNER * (D_CONV - 1)) return;
    int j = idx % (D_CONV - 1);
    int d = (idx / (D_CONV - 1)) % D_INNER;
    int b = idx / (D_INNER * (D_CONV - 1));
    outp[idx] = g_xz[((size_t)b * T_LEN + (T_LEN - (D_CONV - 1) + j)) * (2 * D_INNER) + d];
}

// ----------------------------------------------------------------------------
// Selective scan: 8 threads per (b,d), 2 states each. Register prefetch
// (distance 2) hides per-step memory latency; width-8 shfl reduction for y.
// ----------------------------------------------------------------------------
__global__ void __launch_bounds__(256) scan8(const float* __restrict__ ssm0,
                                             const float* __restrict__ A_log,
                                             const float* __restrict__ D_skip,
                                             float* __restrict__ h_out)
{
    int idx = blockIdx.x * 256 + threadIdx.x;   // 0..32767
    int s = idx & 7;
    int d = (idx >> 3) & (D_INNER - 1);
    int b = idx >> 14;
    int n0 = 2 * s;

    float2 hv = *(const float2*)&ssm0[((size_t)b * D_INNER + d) * D_STATE + n0];
    float2 al = *(const float2*)&A_log[d * D_STATE + n0];
    float A0 = -__expf(al.x), A1 = -__expf(al.y);
    float dsk = D_skip[d];

    const float* dt_p = g_dt    + (size_t)b * T_LEN * D_INNER + d;
    const float* xc_p = g_xconv + (size_t)b * T_LEN * D_INNER + d;
    const float* z_p  = g_xz    + (size_t)b * T_LEN * (2 * D_INNER) + D_INNER + d;
    const float* bc_p = g_proj  + (size_t)b * T_LEN * PROJ_N + DT_RANK + n0;
    float*       y_p  = g_y     + (size_t)b * T_LEN * D_INNER + d;

    float dt_b[2], xc_b[2], z_b[2];
    float2 B_b[2], C_b[2];
#pragma unroll
    for (int p = 0; p < 2; p++) {
        dt_b[p] = dt_p[(size_t)p * D_INNER];
        xc_b[p] = xc_p[(size_t)p * D_INNER];
        z_b[p]  = z_p[(size_t)p * 2 * D_INNER];
        B_b[p]  = *(const float2*)(bc_p + (size_t)p * PROJ_N);
        C_b[p]  = *(const float2*)(bc_p + (size_t)p * PROJ_N + D_STATE);
    }

    for (int t = 0; t < T_LEN; t++) {
        const int cur = t & 1;
        float dt = dt_b[cur], xc = xc_b[cur], z = z_b[cur];
        float2 Bv = B_b[cur], Cv = C_b[cur];
        if (t + 2 < T_LEN) {
            size_t o = (size_t)(t + 2);
            dt_b[cur] = dt_p[o * D_INNER];
            xc_b[cur] = xc_p[o * D_INNER];
            z_b[cur]  = z_p[o * 2 * D_INNER];
            B_b[cur]  = *(const float2*)(bc_p + o * PROJ_N);
            C_b[cur]  = *(const float2*)(bc_p + o * PROJ_N + D_STATE);
        }
        float e0 = __expf(dt * A0);
        float e1 = __expf(dt * A1);
        float dx = dt * xc;
        hv.x = fmaf(e0, hv.x, dx * Bv.x);
        hv.y = fmaf(e1, hv.y, dx * Bv.y);
        float r = fmaf(hv.x, Cv.x, hv.y * Cv.y);
        r += __shfl_xor_sync(0xffffffffu, r, 1, 8);
        r += __shfl_xor_sync(0xffffffffu, r, 2, 8);
        r += __shfl_xor_sync(0xffffffffu, r, 4, 8);
        if (s == 0) {
            float y = fmaf(dsk, xc, r);
            float sz = z / (1.f + __expf(-z));
            y_p[(size_t)t * D_INNER] = y * sz;
        }
    }
    *(float2*)&h_out[((size_t)b * D_INNER + d) * D_STATE + n0] = hv;
}

// ----------------------------------------------------------------------------
extern "C" void kernel_launch(void* const* d_in, const int* in_sizes, int n_in,
                              void* d_out, int out_size)
{
    const float* x          = (const float*)d_in[0];
    const float* ssm_state  = (const float*)d_in[1];
    const float* conv_state = (const float*)d_in[2];
    const float* w_in       = (const float*)d_in[3];
    const float* conv_w     = (const float*)d_in[4];
    const float* conv_b     = (const float*)d_in[5];
    const float* w_x        = (const float*)d_in[6];
    const float* w_dt       = (const float*)d_in[7];
    const float* b_dt       = (const float*)d_in[8];
    const float* A_log      = (const float*)d_in[9];
    const float* D_skip     = (const float*)d_in[10];
    const float* w_out      = (const float*)d_in[11];
    float* out = (float*)d_out;

    float *xz, *xconv, *proj, *projp, *dt, *y;
    cudaGetSymbolAddress((void**)&xz,    g_xz);
    cudaGetSymbolAddress((void**)&xconv, g_xconv);
    cudaGetSymbolAddress((void**)&proj,  g_proj);
    cudaGetSymbolAddress((void**)&projp, g_projp);
    cudaGetSymbolAddress((void**)&dt,    g_dt);
    cudaGetSymbolAddress((void**)&y,     g_y);

    // 1) xz = x @ w_in   (4096 x 1024) @ (1024 x 4096)
    gemm_f2<<<dim3(32, 32, 1), 256>>>(x, DIM, w_in, 2 * D_INNER, xz, 2 * D_INNER,
                                      2 * D_INNER, DIM, 0, nullptr, 0);

    // 2) depthwise conv + silu
    conv_kernel<<<dim3(D_INNER / 256, T_LEN, B_SZ), 256>>>(conv_state, conv_w, conv_b);

    // new conv state
    convstate_kernel<<<(B_SZ * D_INNER * (D_CONV - 1) + 255) / 256, 256>>>(out + OFF_CONV);

    // 3) proj = x_conv @ w_x  (4096 x 2048) @ (2048 x 96), split-K=8 partials
    gemm_f2<<<dim3(1, 32, KSPLIT), 256>>>(xconv, D_INNER, w_x, PROJ_N, projp, PROJ_N,
                                          PROJ_N, D_INNER / KSPLIT,
                                          (size_t)ROWS * PROJ_N, nullptr, 0);
    reduce_proj<<<(ROWS * PROJ_N + 255) / 256, 256>>>();

    // 4) dt = softplus(proj[:, :64] @ w_dt + b_dt)
    gemm_f2<<<dim3(16, 32, 1), 256>>>(proj, PROJ_N, w_dt, D_INNER, dt, D_INNER,
                                      D_INNER, DT_RANK, 0, b_dt, 1);

    // 5) selective scan (writes g_y and h_final)
    scan8<<<(B_SZ * D_INNER * 8) / 256, 256>>>(ssm_state, A_log, D_skip, out + OFF_H);

    // 6) out = y_gated @ w_out  (4096 x 2048) @ (2048 x 1024)
    gemm_f2<<<dim3(8, 32, 1), 256>>>(y, D_INNER, w_out, DIM, out, DIM,
                                     DIM, D_INNER, 0, nullptr, 0);
}

// round 6
// speedup vs baseline: 2.5460x; 1.4068x over previous
#include <cuda_runtime.h>
#include <cuda_bf16.h>
#include <math.h>
#include <stdint.h>

// Problem constants
#define DIM      1024
#define D_INNER  2048
#define D_STATE  16
#define D_CONV   4
#define DT_RANK  64
#define B_SZ     2
#define T_LEN    2048
#define ROWS     (B_SZ * T_LEN)           // 4096
#define PROJ_N   (DT_RANK + 2 * D_STATE)  // 96
#define KSPLIT   4

// Output offsets (floats): out | h_final | new_conv_state
#define OFF_H    (ROWS * DIM)
#define OFF_CONV (OFF_H + B_SZ * D_INNER * D_STATE)

// ---------------- scratch (device globals) ----------------
__device__ float g_xz[(size_t)ROWS * (2 * D_INNER)];   // x_in | z
__device__ float g_xconv[(size_t)ROWS * D_INNER];
__device__ float g_projp[(size_t)KSPLIT * ROWS * PROJ_N];
__device__ float g_proj[(size_t)ROWS * PROJ_N];
__device__ float g_dt[(size_t)ROWS * D_INNER];
// bf16 3-term split operands (K tripled):
//   A side (activations): [hi | lo | hi]
//   B side (weights):     [hi | hi | lo]
__device__ __align__(16) __nv_bfloat16 g_xs  [(size_t)ROWS * (3 * DIM)];
__device__ __align__(16) __nv_bfloat16 g_wint[(size_t)(2 * D_INNER) * (3 * DIM)];
__device__ __align__(16) __nv_bfloat16 g_xcs [(size_t)ROWS * (3 * D_INNER)];
__device__ __align__(16) __nv_bfloat16 g_wxt [(size_t)PROJ_N * (3 * D_INNER)];
__device__ __align__(16) __nv_bfloat16 g_dtin[(size_t)ROWS * (3 * DT_RANK)];
__device__ __align__(16) __nv_bfloat16 g_wdtt[(size_t)D_INNER * (3 * DT_RANK)];
__device__ __align__(16) __nv_bfloat16 g_ys  [(size_t)ROWS * (3 * D_INNER)];
__device__ __align__(16) __nv_bfloat16 g_wott[(size_t)DIM * (3 * D_INNER)];

// ---------------- mma helpers ----------------
__device__ __forceinline__ uint32_t smem_u32(const void* p) {
    uint32_t a;
    asm("{ .reg .u64 t; cvta.to.shared.u64 t, %1; cvt.u32.u64 %0, t; }" : "=r"(a) : "l"(p));
    return a;
}
__device__ __forceinline__ void ldsm_x4(uint32_t addr, uint32_t& r0, uint32_t& r1,
                                        uint32_t& r2, uint32_t& r3) {
    asm volatile("ldmatrix.sync.aligned.m8n8.x4.shared.b16 {%0,%1,%2,%3}, [%4];"
                 : "=r"(r0), "=r"(r1), "=r"(r2), "=r"(r3) : "r"(addr));
}
__device__ __forceinline__ void mma16816(float* d, const uint32_t* a,
                                         uint32_t b0, uint32_t b1) {
    asm volatile("mma.sync.aligned.m16n8k16.row.col.f32.bf16.bf16.f32 "
                 "{%0,%1,%2,%3}, {%4,%5,%6,%7}, {%8,%9}, {%0,%1,%2,%3};"
                 : "+f"(d[0]), "+f"(d[1]), "+f"(d[2]), "+f"(d[3])
                 : "r"(a[0]), "r"(a[1]), "r"(a[2]), "r"(a[3]), "r"(b0), "r"(b1));
}

// ----------------------------------------------------------------------------
// bf16 HMMA GEMM: C[M,N] = A[M,Kp] * Bt[N,Kp]^T. Bt row-major [N][ldb]
// (= B col-major, so the MMA B fragment comes from PLAIN ldmatrix, no .trans).
// 128x128 CTA tile, BK=64, 8 warps (4x2), warp tile 32x64 via m16n8k16.
// Double-buffered smem, 72-elem padded rows. Split-K via gridDim.z (kLen per z,
// output to C + z*zStride). mode 1: +bias[col] then softplus.
// Requirements: M%128==0, kLen%64==0, lda/ldb %8==0, N even.
// ----------------------------------------------------------------------------
#define STRIDE 72
#define STAGE_B 18432u                       // 128*72*2 bytes per matrix
#define GEMM_SMEM (4 * 18432 + 1024)

__global__ void __launch_bounds__(256) gemm_mma(
    const __nv_bfloat16* __restrict__ A, int lda,
    const __nv_bfloat16* __restrict__ Bt, int ldb, int N,
    float* __restrict__ C, int ldc, int kLen, size_t zStride,
    const float* __restrict__ bias, int mode)
{
    extern __shared__ char smraw[];
    const uint32_t sb = (smem_u32(smraw) + 127u) & ~127u;
    const uint32_t sA[2] = { sb, sb + 2 * STAGE_B };
    const uint32_t sB[2] = { sb + STAGE_B, sb + 3 * STAGE_B };

    const int tid = threadIdx.x;
    const int lane = tid & 31;
    const int wid = tid >> 5;
    const int wr = wid >> 1;          // 0..3
    const int wc = wid & 1;           // 0..1
    const int bRow = blockIdx.y << 7;
    const int bCol = blockIdx.x << 7;
    const int kBase = blockIdx.z * kLen;

    const __nv_bfloat16* Ab = A + (size_t)bRow * lda + kBase;

    const int lrow[4] = { (0 * 256 + tid) >> 3, (1 * 256 + tid) >> 3,
                          (2 * 256 + tid) >> 3, (3 * 256 + tid) >> 3 };
    const int lkq = tid & 7;

    float acc[2][8][4];
#pragma unroll
    for (int mi = 0; mi < 2; mi++)
#pragma unroll
        for (int ni = 0; ni < 8; ni++)
#pragma unroll
            for (int e = 0; e < 4; e++) acc[mi][ni][e] = 0.f;

    uint4 ra[4], rb[4];
    const uint4 z4 = make_uint4(0, 0, 0, 0);

#define G_LOAD(c)                                                              \
    do {                                                                       \
        const int k0 = (c) << 6;                                               \
        _Pragma("unroll")                                                      \
        for (int i = 0; i < 4; i++) {                                          \
            ra[i] = *(const uint4*)(Ab + (size_t)lrow[i] * lda + k0 + lkq * 8);\
            const int rbr = bCol + lrow[i];                                    \
            rb[i] = (rbr < N)                                                  \
                ? *(const uint4*)(Bt + (size_t)rbr * ldb + kBase + k0 + lkq * 8)\
                : z4;                                                          \
        }                                                                      \
    } while (0)

#define S_STORE(s)                                                             \
    do {                                                                       \
        _Pragma("unroll")                                                      \
        for (int i = 0; i < 4; i++) {                                          \
            const uint32_t off = ((uint32_t)lrow[i] * STRIDE + lkq * 8) * 2;   \
            asm volatile("st.shared.v4.b32 [%0], {%1,%2,%3,%4};" ::            \
                "r"(sA[s] + off), "r"(ra[i].x), "r"(ra[i].y),                  \
                "r"(ra[i].z), "r"(ra[i].w));                                   \
            asm volatile("st.shared.v4.b32 [%0], {%1,%2,%3,%4};" ::            \
                "r"(sB[s] + off), "r"(rb[i].x), "r"(rb[i].y),                  \
                "r"(rb[i].z), "r"(rb[i].w));                                   \
        }                                                                      \
    } while (0)

    const int nchunk = kLen >> 6;
    G_LOAD(0);
    S_STORE(0);
    __syncthreads();

    // ldmatrix lane address components
    const uint32_t aRow = (uint32_t)(wr * 32 + (lane & 7) + ((lane >> 3) & 1) * 8);
    const uint32_t aKof = (uint32_t)((lane >> 4) * 8);
    const uint32_t bRowL = (uint32_t)(wc * 64 + (lane & 7) + ((lane >> 4) << 3));
    const uint32_t bKof = (uint32_t)(((lane >> 3) & 1) * 8);

    for (int c = 0; c < nchunk; c++) {
        const int s = c & 1;
        const bool pf = (c + 1) < nchunk;
        if (pf) G_LOAD(c + 1);

#pragma unroll
        for (int ks = 0; ks < 4; ks++) {
            uint32_t afr[2][4];
#pragma unroll
            for (int mi = 0; mi < 2; mi++) {
                uint32_t ad = sA[s] + ((aRow + mi * 16) * STRIDE + ks * 16 + aKof) * 2;
                ldsm_x4(ad, afr[mi][0], afr[mi][1], afr[mi][2], afr[mi][3]);
            }
            uint32_t bfr[8][2];
#pragma unroll
            for (int nq = 0; nq < 4; nq++) {
                uint32_t bd = sB[s] + ((bRowL + nq * 16) * STRIDE + ks * 16 + bKof) * 2;
                uint32_t r0, r1, r2, r3;
                ldsm_x4(bd, r0, r1, r2, r3);   // non-trans: Bt rows ARE col-major B
                bfr[nq * 2][0] = r0; bfr[nq * 2][1] = r1;
                bfr[nq * 2 + 1][0] = r2; bfr[nq * 2 + 1][1] = r3;
            }
#pragma unroll
            for (int mi = 0; mi < 2; mi++)
#pragma unroll
                for (int ni = 0; ni < 8; ni++)
                    mma16816(acc[mi][ni], afr[mi], bfr[ni][0], bfr[ni][1]);
        }
        if (pf) {
            __syncthreads();
            S_STORE((c + 1) & 1);
            __syncthreads();
        }
    }

    // epilogue
    float* Cz = C + (size_t)blockIdx.z * zStride;
#pragma unroll
    for (int mi = 0; mi < 2; mi++) {
#pragma unroll
        for (int ni = 0; ni < 8; ni++) {
            const int col = bCol + wc * 64 + ni * 8 + (lane & 3) * 2;
            if (col >= N) continue;
            const int r0 = bRow + wr * 32 + mi * 16 + (lane >> 2);
            float v0 = acc[mi][ni][0], v1 = acc[mi][ni][1];
            float v2 = acc[mi][ni][2], v3 = acc[mi][ni][3];
            if (mode == 1) {
                float b0 = bias[col], b1 = bias[col + 1];
                v0 += b0; v1 += b1; v2 += b0; v3 += b1;
                v0 = (v0 > 20.f) ? v0 : log1pf(__expf(v0));
                v1 = (v1 > 20.f) ? v1 : log1pf(__expf(v1));
                v2 = (v2 > 20.f) ? v2 : log1pf(__expf(v2));
                v3 = (v3 > 20.f) ? v3 : log1pf(__expf(v3));
            }
            *(float2*)&Cz[(size_t)r0 * ldc + col] = make_float2(v0, v1);
            *(float2*)&Cz[(size_t)(r0 + 8) * ldc + col] = make_float2(v2, v3);
        }
    }
}

// reduce split-K partials of proj
__global__ void reduce_proj()
{
    int i = blockIdx.x * 256 + threadIdx.x;
    if (i >= ROWS * PROJ_N) return;
    float s = 0.f;
#pragma unroll
    for (int p = 0; p < KSPLIT; p++) s += g_projp[(size_t)p * ROWS * PROJ_N + i];
    g_proj[i] = s;
}

// ---------------- conversion kernels ----------------
// A-side split: in f32 [M][K] (row stride ldin) -> out bf16 [M][3K] = [hi|lo|hi]
__global__ void rsplit(const float* __restrict__ in, int ldin, int M, int K,
                       __nv_bfloat16* __restrict__ out)
{
    int i = blockIdx.x * 256 + threadIdx.x;
    if (i >= M * K) return;
    int m = i / K, k = i - m * K;
    float v = in[(size_t)m * ldin + k];
    __nv_bfloat16 h = __float2bfloat16(v);
    __nv_bfloat16 l = __float2bfloat16(v - __bfloat162float(h));
    size_t base = (size_t)m * (3 * K);
    out[base + k] = h;
    out[base + K + k] = l;
    out[base + 2 * K + k] = h;
}

// B-side transpose + split: in f32 [K][N] -> out bf16 [N][3K] = [hi|hi|lo]
__global__ void tsplit(const float* __restrict__ in, int K, int N,
                       __nv_bfloat16* __restrict__ out)
{
    __shared__ float t[32][33];
    int k0 = blockIdx.y * 32, n0 = blockIdx.x * 32;
    int k = k0 + threadIdx.y, n = n0 + threadIdx.x;
    t[threadIdx.y][threadIdx.x] = (k < K && n < N) ? in[(size_t)k * N + n] : 0.f;
    __syncthreads();
    int on = n0 + threadIdx.y, ok = k0 + threadIdx.x;
    if (on < N && ok < K) {
        float v = t[threadIdx.x][threadIdx.y];
        __nv_bfloat16 h = __float2bfloat16(v);
        __nv_bfloat16 l = __float2bfloat16(v - __bfloat162float(h));
        size_t base = (size_t)on * (3 * K);
        out[base + ok] = h;
        out[base + K + ok] = h;
        out[base + 2 * K + ok] = l;
    }
}

// ---------------- conv + silu (emits fp32 + A-side bf16 split) ----------------
__global__ void conv_kernel(const float* __restrict__ conv_state,
                            const float* __restrict__ conv_w,
                            const float* __restrict__ conv_b)
{
    int d = blockIdx.x * 256 + threadIdx.x;
    int t = blockIdx.y;
    int b = blockIdx.z;

    float acc = conv_b[d];
#pragma unroll
    for (int k = 0; k < D_CONV; k++) {
        int i = t + k;
        float v;
        if (i < D_CONV - 1)
            v = conv_state[((size_t)b * D_INNER + d) * (D_CONV - 1) + i];
        else
            v = g_xz[((size_t)b * T_LEN + (i - (D_CONV - 1))) * (2 * D_INNER) + d];
        acc = fmaf(conv_w[d * D_CONV + k], v, acc);
    }
    float sig = 1.f / (1.f + __expf(-acc));
    float r = acc * sig;
    size_t row = (size_t)b * T_LEN + t;
    g_xconv[row * D_INNER + d] = r;
    __nv_bfloat16 h = __float2bfloat16(r);
    __nv_bfloat16 l = __float2bfloat16(r - __bfloat162float(h));
    size_t base = row * (3 * D_INNER);
    g_xcs[base + d] = h;
    g_xcs[base + D_INNER + d] = l;
    g_xcs[base + 2 * D_INNER + d] = h;
}

__global__ void convstate_kernel(float* __restrict__ outp)
{
    int idx = blockIdx.x * 256 + threadIdx.x;
    if (idx >= B_SZ * D_INNER * (D_CONV - 1)) return;
    int j = idx % (D_CONV - 1);
    int d = (idx / (D_CONV - 1)) % D_INNER;
    int b = idx / (D_INNER * (D_CONV - 1));
    outp[idx] = g_xz[((size_t)b * T_LEN + (T_LEN - (D_CONV - 1) + j)) * (2 * D_INNER) + d];
}

// ---------------- selective scan (emits A-side bf16 split y) ----------------
__global__ void __launch_bounds__(256) scan8(const float* __restrict__ ssm0,
                                             const float* __restrict__ A_log,
                                             const float* __restrict__ D_skip,
                                             float* __restrict__ h_out)
{
    int idx = blockIdx.x * 256 + threadIdx.x;
    int s = idx & 7;
    int d = (idx >> 3) & (D_INNER - 1);
    int b = idx >> 14;
    int n0 = 2 * s;

    float2 hv = *(const float2*)&ssm0[((size_t)b * D_INNER + d) * D_STATE + n0];
    float2 al = *(const float2*)&A_log[d * D_STATE + n0];
    float A0 = -__expf(al.x), A1 = -__expf(al.y);
    float dsk = D_skip[d];

    const float* dt_p = g_dt    + (size_t)b * T_LEN * D_INNER + d;
    const float* xc_p = g_xconv + (size_t)b * T_LEN * D_INNER + d;
    const float* z_p  = g_xz    + (size_t)b * T_LEN * (2 * D_INNER) + D_INNER + d;
    const float* bc_p = g_proj  + (size_t)b * T_LEN * PROJ_N + DT_RANK + n0;
    __nv_bfloat16* ys = g_ys    + (size_t)b * T_LEN * (3 * D_INNER) + d;

    float dt_b[2], xc_b[2], z_b[2];
    float2 B_b[2], C_b[2];
#pragma unroll
    for (int p = 0; p < 2; p++) {
        dt_b[p] = dt_p[(size_t)p * D_INNER];
        xc_b[p] = xc_p[(size_t)p * D_INNER];
        z_b[p]  = z_p[(size_t)p * 2 * D_INNER];
        B_b[p]  = *(const float2*)(bc_p + (size_t)p * PROJ_N);
        C_b[p]  = *(const float2*)(bc_p + (size_t)p * PROJ_N + D_STATE);
    }

    for (int t = 0; t < T_LEN; t++) {
        const int cur = t & 1;
        float dt = dt_b[cur], xc = xc_b[cur], z = z_b[cur];
        float2 Bv = B_b[cur], Cv = C_b[cur];
        if (t + 2 < T_LEN) {
            size_t o = (size_t)(t + 2);
            dt_b[cur] = dt_p[o * D_INNER];
            xc_b[cur] = xc_p[o * D_INNER];
            z_b[cur]  = z_p[o * 2 * D_INNER];
            B_b[cur]  = *(const float2*)(bc_p + o * PROJ_N);
            C_b[cur]  = *(const float2*)(bc_p + o * PROJ_N + D_STATE);
        }
        float e0 = __expf(dt * A0);
        float e1 = __expf(dt * A1);
        float dx = dt * xc;
        hv.x = fmaf(e0, hv.x, dx * Bv.x);
        hv.y = fmaf(e1, hv.y, dx * Bv.y);
        float r = fmaf(hv.x, Cv.x, hv.y * Cv.y);
        r += __shfl_xor_sync(0xffffffffu, r, 1, 8);
        r += __shfl_xor_sync(0xffffffffu, r, 2, 8);
        r += __shfl_xor_sync(0xffffffffu, r, 4, 8);
        if (s == 0) {
            float yv = fmaf(dsk, xc, r);
            float sz = z / (1.f + __expf(-z));
            yv *= sz;
            __nv_bfloat16 h = __float2bfloat16(yv);
            __nv_bfloat16 l = __float2bfloat16(yv - __bfloat162float(h));
            size_t base = (size_t)t * (3 * D_INNER);
            ys[base] = h;
            ys[base + D_INNER] = l;
            ys[base + 2 * D_INNER] = h;
        }
    }
    *(float2*)&h_out[((size_t)b * D_INNER + d) * D_STATE + n0] = hv;
}

// ----------------------------------------------------------------------------
extern "C" void kernel_launch(void* const* d_in, const int* in_sizes, int n_in,
                              void* d_out, int out_size)
{
    const float* x          = (const float*)d_in[0];
    const float* ssm_state  = (const float*)d_in[1];
    const float* conv_state = (const float*)d_in[2];
    const float* w_in       = (const float*)d_in[3];
    const float* conv_w     = (const float*)d_in[4];
    const float* conv_b     = (const float*)d_in[5];
    const float* w_x        = (const float*)d_in[6];
    const float* w_dt       = (const float*)d_in[7];
    const float* b_dt       = (const float*)d_in[8];
    const float* A_log      = (const float*)d_in[9];
    const float* D_skip     = (const float*)d_in[10];
    const float* w_out      = (const float*)d_in[11];
    float* out = (float*)d_out;

    cudaStreamCaptureStatus cs = cudaStreamCaptureStatusNone;
    cudaStreamIsCapturing(cudaStreamLegacy, &cs);
    if (cs == cudaStreamCaptureStatusNone)
        cudaFuncSetAttribute(gemm_mma, cudaFuncAttributeMaxDynamicSharedMemorySize, GEMM_SMEM);

    float *xz, *proj, *projp, *dt;
    __nv_bfloat16 *xs, *wint, *xcs, *wxt, *dtin, *wdtt, *ys, *wott;
    cudaGetSymbolAddress((void**)&xz,    g_xz);
    cudaGetSymbolAddress((void**)&proj,  g_proj);
    cudaGetSymbolAddress((void**)&projp, g_projp);
    cudaGetSymbolAddress((void**)&dt,    g_dt);
    cudaGetSymbolAddress((void**)&xs,    g_xs);
    cudaGetSymbolAddress((void**)&wint,  g_wint);
    cudaGetSymbolAddress((void**)&xcs,   g_xcs);
    cudaGetSymbolAddress((void**)&wxt,   g_wxt);
    cudaGetSymbolAddress((void**)&dtin,  g_dtin);
    cudaGetSymbolAddress((void**)&wdtt,  g_wdtt);
    cudaGetSymbolAddress((void**)&ys,    g_ys);
    cudaGetSymbolAddress((void**)&wott,  g_wott);

    // conversions (3-term split; weights transposed)
    rsplit<<<(ROWS * DIM + 255) / 256, 256>>>(x, DIM, ROWS, DIM, xs);
    tsplit<<<dim3((2 * D_INNER) / 32, DIM / 32), dim3(32, 32)>>>(w_in, DIM, 2 * D_INNER, wint);
    tsplit<<<dim3(3, D_INNER / 32), dim3(32, 32)>>>(w_x, D_INNER, PROJ_N, wxt);
    tsplit<<<dim3(D_INNER / 32, 2), dim3(32, 32)>>>(w_dt, DT_RANK, D_INNER, wdtt);
    tsplit<<<dim3(DIM / 32, D_INNER / 32), dim3(32, 32)>>>(w_out, D_INNER, DIM, wott);

    // 1) xz = x @ w_in   (Kp = 3*1024 = 3072)
    gemm_mma<<<dim3(32, 32, 1), 256, GEMM_SMEM>>>(
        xs, 3 * DIM, wint, 3 * DIM, 2 * D_INNER,
        xz, 2 * D_INNER, 3 * DIM, 0, nullptr, 0);

    // 2) depthwise conv + silu
    conv_kernel<<<dim3(D_INNER / 256, T_LEN, B_SZ), 256>>>(conv_state, conv_w, conv_b);
    convstate_kernel<<<(B_SZ * D_INNER * (D_CONV - 1) + 255) / 256, 256>>>(out + OFF_CONV);

    // 3) proj = x_conv @ w_x  (Kp = 6144, split-K=4 -> 1536 per z)
    gemm_mma<<<dim3(1, 32, KSPLIT), 256, GEMM_SMEM>>>(
        xcs, 3 * D_INNER, wxt, 3 * D_INNER, PROJ_N,
        projp, PROJ_N, (3 * D_INNER) / KSPLIT, (size_t)ROWS * PROJ_N, nullptr, 0);
    reduce_proj<<<(ROWS * PROJ_N + 255) / 256, 256>>>();

    // 4) dt = softplus(proj[:, :64] @ w_dt + b_dt)  (Kp = 192)
    rsplit<<<(ROWS * DT_RANK + 255) / 256, 256>>>(proj, PROJ_N, ROWS, DT_RANK, dtin);
    gemm_mma<<<dim3(16, 32, 1), 256, GEMM_SMEM>>>(
        dtin, 3 * DT_RANK, wdtt, 3 * DT_RANK, D_INNER,
        dt, D_INNER, 3 * DT_RANK, 0, b_dt, 1);

    // 5) selective scan
    scan8<<<(B_SZ * D_INNER * 8) / 256, 256>>>(ssm_state, A_log, D_skip, out + OFF_H);

    // 6) out = y_gated @ w_out  (Kp = 6144)
    gemm_mma<<<dim3(8, 32, 1), 256, GEMM_SMEM>>>(
        ys, 3 * D_INNER, wott, 3 * D_INNER, DIM,
        out, DIM, 3 * D_INNER, 0, nullptr, 0);
}

// round 7
// speedup vs baseline: 2.5701x; 1.0095x over previous
#include <cuda_runtime.h>
#include <cuda_bf16.h>
#include <math.h>
#include <stdint.h>

// Problem constants
#define DIM      1024
#define D_INNER  2048
#define D_STATE  16
#define D_CONV   4
#define DT_RANK  64
#define B_SZ     2
#define T_LEN    2048
#define ROWS     (B_SZ * T_LEN)           // 4096
#define PROJ_N   (DT_RANK + 2 * D_STATE)  // 96
#define KSPLIT   4

// Output offsets (floats): out | h_final | new_conv_state
#define OFF_H    (ROWS * DIM)
#define OFF_CONV (OFF_H + B_SZ * D_INNER * D_STATE)

// ---------------- scratch (device globals) ----------------
__device__ float g_xz[(size_t)ROWS * (2 * D_INNER)];   // x_in | z
__device__ float g_xconv[(size_t)ROWS * D_INNER];
__device__ float g_projp[(size_t)KSPLIT * ROWS * PROJ_N];
__device__ float g_proj[(size_t)ROWS * PROJ_N];
__device__ float g_dt[(size_t)ROWS * D_INNER];
// bf16 3-term split operands (K tripled):
//   A side (activations): [hi | lo | hi]
//   B side (weights):     [hi | hi | lo]
__device__ __align__(16) __nv_bfloat16 g_xs  [(size_t)ROWS * (3 * DIM)];
__device__ __align__(16) __nv_bfloat16 g_wint[(size_t)(2 * D_INNER) * (3 * DIM)];
__device__ __align__(16) __nv_bfloat16 g_xcs [(size_t)ROWS * (3 * D_INNER)];
__device__ __align__(16) __nv_bfloat16 g_wxt [(size_t)PROJ_N * (3 * D_INNER)];
__device__ __align__(16) __nv_bfloat16 g_dtin[(size_t)ROWS * (3 * DT_RANK)];
__device__ __align__(16) __nv_bfloat16 g_wdtt[(size_t)D_INNER * (3 * DT_RANK)];
__device__ __align__(16) __nv_bfloat16 g_ys  [(size_t)ROWS * (3 * D_INNER)];
__device__ __align__(16) __nv_bfloat16 g_wott[(size_t)DIM * (3 * D_INNER)];

// ---------------- mma helpers ----------------
__device__ __forceinline__ uint32_t smem_u32(const void* p) {
    uint32_t a;
    asm("{ .reg .u64 t; cvta.to.shared.u64 t, %1; cvt.u32.u64 %0, t; }" : "=r"(a) : "l"(p));
    return a;
}
__device__ __forceinline__ void ldsm_x4(uint32_t addr, uint32_t& r0, uint32_t& r1,
                                        uint32_t& r2, uint32_t& r3) {
    asm volatile("ldmatrix.sync.aligned.m8n8.x4.shared.b16 {%0,%1,%2,%3}, [%4];"
                 : "=r"(r0), "=r"(r1), "=r"(r2), "=r"(r3) : "r"(addr));
}
__device__ __forceinline__ void mma16816(float* d, const uint32_t* a,
                                         uint32_t b0, uint32_t b1) {
    asm volatile("mma.sync.aligned.m16n8k16.row.col.f32.bf16.bf16.f32 "
                 "{%0,%1,%2,%3}, {%4,%5,%6,%7}, {%8,%9}, {%0,%1,%2,%3};"
                 : "+f"(d[0]), "+f"(d[1]), "+f"(d[2]), "+f"(d[3])
                 : "r"(a[0]), "r"(a[1]), "r"(a[2]), "r"(a[3]), "r"(b0), "r"(b1));
}

// ----------------------------------------------------------------------------
// bf16 HMMA GEMM with cp.async 4-stage pipeline.
// C[M,N] = A[M,Kp] * Bt[N,Kp]^T. Bt row-major [N][ldb] (= B col-major, so the
// MMA B fragment comes from PLAIN ldmatrix, no .trans).
// 128x128 CTA tile, BK=64, 8 warps (4x2), warp tile 32x64 via m16n8k16.
// Split-K via gridDim.z (kLen per z, output to C + z*zStride).
// mode 1: +bias[col] then softplus.
// Requirements: M%128==0, kLen%64==0, lda/ldb %8==0, N even.
// ----------------------------------------------------------------------------
#define STRIDE  72
#define STAGE_B 18432u                       // 128*72*2 bytes per matrix
#define STAGE_T 36864u                       // A + B per stage
#define STAGES  4
#define GEMM_SMEM (4 * 36864 + 256)

__global__ void __launch_bounds__(256) gemm_mma(
    const __nv_bfloat16* __restrict__ A, int lda,
    const __nv_bfloat16* __restrict__ Bt, int ldb, int N,
    float* __restrict__ C, int ldc, int kLen, size_t zStride,
    const float* __restrict__ bias, int mode)
{
    extern __shared__ char smraw[];
    const uint32_t sb = (smem_u32(smraw) + 127u) & ~127u;

    const int tid = threadIdx.x;
    const int lane = tid & 31;
    const int wid = tid >> 5;
    const int wr = wid >> 1;          // 0..3
    const int wc = wid & 1;           // 0..1
    const int bRow = blockIdx.y << 7;
    const int bCol = blockIdx.x << 7;
    const int kBase = blockIdx.z * kLen;

    const __nv_bfloat16* Ab = A + (size_t)bRow * lda + kBase;

    const int lrow[4] = { (0 * 256 + tid) >> 3, (1 * 256 + tid) >> 3,
                          (2 * 256 + tid) >> 3, (3 * 256 + tid) >> 3 };
    const int lkq = tid & 7;

    float acc[2][8][4];
#pragma unroll
    for (int mi = 0; mi < 2; mi++)
#pragma unroll
        for (int ni = 0; ni < 8; ni++)
#pragma unroll
            for (int e = 0; e < 4; e++) acc[mi][ni][e] = 0.f;

// async copy one 64-K chunk into stage (cidx & 3)
#define S_COPY(cidx)                                                           \
    do {                                                                       \
        const int s_ = (cidx) & (STAGES - 1);                                  \
        const int k0_ = (cidx) << 6;                                           \
        const uint32_t sa_ = sb + (uint32_t)s_ * STAGE_T;                      \
        const uint32_t sb_ = sa_ + STAGE_B;                                    \
        _Pragma("unroll")                                                      \
        for (int i = 0; i < 4; i++) {                                          \
            const uint32_t off = ((uint32_t)lrow[i] * STRIDE + lkq * 8) * 2;   \
            const __nv_bfloat16* ga =                                          \
                Ab + (size_t)lrow[i] * lda + k0_ + lkq * 8;                    \
            asm volatile("cp.async.cg.shared.global [%0], [%1], 16;"           \
                         :: "r"(sa_ + off), "l"(ga));                          \
            const int rbr = bCol + lrow[i];                                    \
            const __nv_bfloat16* gb =                                          \
                Bt + (size_t)(rbr < N ? rbr : N - 1) * ldb + kBase + k0_ + lkq * 8; \
            const uint32_t bsz = (rbr < N) ? 16u : 0u;                         \
            asm volatile("cp.async.cg.shared.global [%0], [%1], 16, %2;"       \
                         :: "r"(sb_ + off), "l"(gb), "r"(bsz));                \
        }                                                                      \
    } while (0)

    const int nchunk = kLen >> 6;
    int cread = 0;
#pragma unroll
    for (int i = 0; i < STAGES - 1; i++) {
        if (cread < nchunk) { S_COPY(cread); cread++; }
        asm volatile("cp.async.commit_group;" ::: "memory");
    }

    // ldmatrix lane address components
    const uint32_t aRow = (uint32_t)(wr * 32 + (lane & 7) + ((lane >> 3) & 1) * 8);
    const uint32_t aKof = (uint32_t)((lane >> 4) * 8);
    const uint32_t bRowL = (uint32_t)(wc * 64 + (lane & 7) + ((lane >> 4) << 3));
    const uint32_t bKof = (uint32_t)(((lane >> 3) & 1) * 8);

    for (int c = 0; c < nchunk; c++) {
        asm volatile("cp.async.wait_group %0;" :: "n"(STAGES - 2) : "memory");
        __syncthreads();

        // issue copy for chunk c+STAGES-1 (into the stage freed last iteration)
        if (cread < nchunk) { S_COPY(cread); cread++; }
        asm volatile("cp.async.commit_group;" ::: "memory");

        const int s = c & (STAGES - 1);
        const uint32_t sAs = sb + (uint32_t)s * STAGE_T;
        const uint32_t sBs = sAs + STAGE_B;

#pragma unroll
        for (int ks = 0; ks < 4; ks++) {
            uint32_t afr[2][4];
#pragma unroll
            for (int mi = 0; mi < 2; mi++) {
                uint32_t ad = sAs + ((aRow + mi * 16) * STRIDE + ks * 16 + aKof) * 2;
                ldsm_x4(ad, afr[mi][0], afr[mi][1], afr[mi][2], afr[mi][3]);
            }
            uint32_t bfr[8][2];
#pragma unroll
            for (int nq = 0; nq < 4; nq++) {
                uint32_t bd = sBs + ((bRowL + nq * 16) * STRIDE + ks * 16 + bKof) * 2;
                uint32_t r0, r1, r2, r3;
                ldsm_x4(bd, r0, r1, r2, r3);   // non-trans: Bt rows ARE col-major B
                bfr[nq * 2][0] = r0; bfr[nq * 2][1] = r1;
                bfr[nq * 2 + 1][0] = r2; bfr[nq * 2 + 1][1] = r3;
            }
#pragma unroll
            for (int mi = 0; mi < 2; mi++)
#pragma unroll
                for (int ni = 0; ni < 8; ni++)
                    mma16816(acc[mi][ni], afr[mi], bfr[ni][0], bfr[ni][1]);
        }
    }

    // epilogue
    float* Cz = C + (size_t)blockIdx.z * zStride;
#pragma unroll
    for (int mi = 0; mi < 2; mi++) {
#pragma unroll
        for (int ni = 0; ni < 8; ni++) {
            const int col = bCol + wc * 64 + ni * 8 + (lane & 3) * 2;
            if (col >= N) continue;
            const int r0 = bRow + wr * 32 + mi * 16 + (lane >> 2);
            float v0 = acc[mi][ni][0], v1 = acc[mi][ni][1];
            float v2 = acc[mi][ni][2], v3 = acc[mi][ni][3];
            if (mode == 1) {
                float b0 = bias[col], b1 = bias[col + 1];
                v0 += b0; v1 += b1; v2 += b0; v3 += b1;
                v0 = (v0 > 20.f) ? v0 : log1pf(__expf(v0));
                v1 = (v1 > 20.f) ? v1 : log1pf(__expf(v1));
                v2 = (v2 > 20.f) ? v2 : log1pf(__expf(v2));
                v3 = (v3 > 20.f) ? v3 : log1pf(__expf(v3));
            }
            *(float2*)&Cz[(size_t)r0 * ldc + col] = make_float2(v0, v1);
            *(float2*)&Cz[(size_t)(r0 + 8) * ldc + col] = make_float2(v2, v3);
        }
    }
}

// reduce split-K partials of proj
__global__ void reduce_proj()
{
    int i = blockIdx.x * 256 + threadIdx.x;
    if (i >= ROWS * PROJ_N) return;
    float s = 0.f;
#pragma unroll
    for (int p = 0; p < KSPLIT; p++) s += g_projp[(size_t)p * ROWS * PROJ_N + i];
    g_proj[i] = s;
}

// ---------------- conversion kernels ----------------
// A-side split: in f32 [M][K] (row stride ldin) -> out bf16 [M][3K] = [hi|lo|hi]
__global__ void rsplit(const float* __restrict__ in, int ldin, int M, int K,
                       __nv_bfloat16* __restrict__ out)
{
    int i = blockIdx.x * 256 + threadIdx.x;
    if (i >= M * K) return;
    int m = i / K, k = i - m * K;
    float v = in[(size_t)m * ldin + k];
    __nv_bfloat16 h = __float2bfloat16(v);
    __nv_bfloat16 l = __float2bfloat16(v - __bfloat162float(h));
    size_t base = (size_t)m * (3 * K);
    out[base + k] = h;
    out[base + K + k] = l;
    out[base + 2 * K + k] = h;
}

// B-side transpose + split: in f32 [K][N] -> out bf16 [N][3K] = [hi|hi|lo]
__global__ void tsplit(const float* __restrict__ in, int K, int N,
                       __nv_bfloat16* __restrict__ out)
{
    __shared__ float t[32][33];
    int k0 = blockIdx.y * 32, n0 = blockIdx.x * 32;
    int k = k0 + threadIdx.y, n = n0 + threadIdx.x;
    t[threadIdx.y][threadIdx.x] = (k < K && n < N) ? in[(size_t)k * N + n] : 0.f;
    __syncthreads();
    int on = n0 + threadIdx.y, ok = k0 + threadIdx.x;
    if (on < N && ok < K) {
        float v = t[threadIdx.x][threadIdx.y];
        __nv_bfloat16 h = __float2bfloat16(v);
        __nv_bfloat16 l = __float2bfloat16(v - __bfloat162float(h));
        size_t base = (size_t)on * (3 * K);
        out[base + ok] = h;
        out[base + K + ok] = h;
        out[base + 2 * K + ok] = l;
    }
}

// ---------------- conv + silu: sliding-window, 64 t-steps per thread -------
#define CONV_TT 64
__global__ void __launch_bounds__(256) conv_kernel(
    const float* __restrict__ conv_state,
    const float* __restrict__ conv_w,
    const float* __restrict__ conv_b)
{
    const int d = blockIdx.x * 256 + threadIdx.x;
    const int t0 = blockIdx.y * CONV_TT;
    const int b = blockIdx.z;

    const float w0 = conv_w[d * D_CONV + 0];
    const float w1 = conv_w[d * D_CONV + 1];
    const float w2 = conv_w[d * D_CONV + 2];
    const float w3 = conv_w[d * D_CONV + 3];
    const float cb = conv_b[d];

    const float* xin = g_xz + (size_t)b * T_LEN * (2 * D_INNER) + d;

    float v0, v1, v2;   // x_in at t0-3, t0-2, t0-1 (conv_state if t<0)
    if (t0 == 0) {
        v0 = conv_state[((size_t)b * D_INNER + d) * (D_CONV - 1) + 0];
        v1 = conv_state[((size_t)b * D_INNER + d) * (D_CONV - 1) + 1];
        v2 = conv_state[((size_t)b * D_INNER + d) * (D_CONV - 1) + 2];
    } else {
        v0 = xin[(size_t)(t0 - 3) * (2 * D_INNER)];
        v1 = xin[(size_t)(t0 - 2) * (2 * D_INNER)];
        v2 = xin[(size_t)(t0 - 1) * (2 * D_INNER)];
    }

    float* xcv = g_xconv + (size_t)b * T_LEN * D_INNER + d;
    __nv_bfloat16* xcs = g_xcs + (size_t)b * T_LEN * (3 * D_INNER) + d;

#pragma unroll 4
    for (int i = 0; i < CONV_TT; i++) {
        const int t = t0 + i;
        const float xn = xin[(size_t)t * (2 * D_INNER)];
        float acc = cb;
        acc = fmaf(w0, v0, acc);
        acc = fmaf(w1, v1, acc);
        acc = fmaf(w2, v2, acc);
        acc = fmaf(w3, xn, acc);
        const float sig = 1.f / (1.f + __expf(-acc));
        const float r = acc * sig;
        xcv[(size_t)t * D_INNER] = r;
        const __nv_bfloat16 h = __float2bfloat16(r);
        const __nv_bfloat16 l = __float2bfloat16(r - __bfloat162float(h));
        const size_t base = (size_t)t * (3 * D_INNER);
        xcs[base] = h;
        xcs[base + D_INNER] = l;
        xcs[base + 2 * D_INNER] = h;
        v0 = v1; v1 = v2; v2 = xn;
    }
}

__global__ void convstate_kernel(float* __restrict__ outp)
{
    int idx = blockIdx.x * 256 + threadIdx.x;
    if (idx >= B_SZ * D_INNER * (D_CONV - 1)) return;
    int j = idx % (D_CONV - 1);
    int d = (idx / (D_CONV - 1)) % D_INNER;
    int b = idx / (D_INNER * (D_CONV - 1));
    outp[idx] = g_xz[((size_t)b * T_LEN + (T_LEN - (D_CONV - 1) + j)) * (2 * D_INNER) + d];
}

// ---------------- selective scan (emits A-side bf16 split y) ----------------
__global__ void __launch_bounds__(256) scan8(const float* __restrict__ ssm0,
                                             const float* __restrict__ A_log,
                                             const float* __restrict__ D_skip,
                                             float* __restrict__ h_out)
{
    int idx = blockIdx.x * 256 + threadIdx.x;
    int s = idx & 7;
    int d = (idx >> 3) & (D_INNER - 1);
    int b = idx >> 14;
    int n0 = 2 * s;

    float2 hv = *(const float2*)&ssm0[((size_t)b * D_INNER + d) * D_STATE + n0];
    float2 al = *(const float2*)&A_log[d * D_STATE + n0];
    float A0 = -__expf(al.x), A1 = -__expf(al.y);
    float dsk = D_skip[d];

    const float* dt_p = g_dt    + (size_t)b * T_LEN * D_INNER + d;
    const float* xc_p = g_xconv + (size_t)b * T_LEN * D_INNER + d;
    const float* z_p  = g_xz    + (size_t)b * T_LEN * (2 * D_INNER) + D_INNER + d;
    const float* bc_p = g_proj  + (size_t)b * T_LEN * PROJ_N + DT_RANK + n0;
    __nv_bfloat16* ys = g_ys    + (size_t)b * T_LEN * (3 * D_INNER) + d;

    float dt_b[2], xc_b[2], z_b[2];
    float2 B_b[2], C_b[2];
#pragma unroll
    for (int p = 0; p < 2; p++) {
        dt_b[p] = dt_p[(size_t)p * D_INNER];
        xc_b[p] = xc_p[(size_t)p * D_INNER];
        z_b[p]  = z_p[(size_t)p * 2 * D_INNER];
        B_b[p]  = *(const float2*)(bc_p + (size_t)p * PROJ_N);
        C_b[p]  = *(const float2*)(bc_p + (size_t)p * PROJ_N + D_STATE);
    }

    for (int t = 0; t < T_LEN; t++) {
        const int cur = t & 1;
        float dt = dt_b[cur], xc = xc_b[cur], z = z_b[cur];
        float2 Bv = B_b[cur], Cv = C_b[cur];
        if (t + 2 < T_LEN) {
            size_t o = (size_t)(t + 2);
            dt_b[cur] = dt_p[o * D_INNER];
            xc_b[cur] = xc_p[o * D_INNER];
            z_b[cur]  = z_p[o * 2 * D_INNER];
            B_b[cur]  = *(const float2*)(bc_p + o * PROJ_N);
            C_b[cur]  = *(const float2*)(bc_p + o * PROJ_N + D_STATE);
        }
        float e0 = __expf(dt * A0);
        float e1 = __expf(dt * A1);
        float dx = dt * xc;
        hv.x = fmaf(e0, hv.x, dx * Bv.x);
        hv.y = fmaf(e1, hv.y, dx * Bv.y);
        float r = fmaf(hv.x, Cv.x, hv.y * Cv.y);
        r += __shfl_xor_sync(0xffffffffu, r, 1, 8);
        r += __shfl_xor_sync(0xffffffffu, r, 2, 8);
        r += __shfl_xor_sync(0xffffffffu, r, 4, 8);
        if (s == 0) {
            float yv = fmaf(dsk, xc, r);
            float sz = z / (1.f + __expf(-z));
            yv *= sz;
            __nv_bfloat16 h = __float2bfloat16(yv);
            __nv_bfloat16 l = __float2bfloat16(yv - __bfloat162float(h));
            size_t base = (size_t)t * (3 * D_INNER);
            ys[base] = h;
            ys[base + D_INNER] = l;
            ys[base + 2 * D_INNER] = h;
        }
    }
    *(float2*)&h_out[((size_t)b * D_INNER + d) * D_STATE + n0] = hv;
}

// ----------------------------------------------------------------------------
extern "C" void kernel_launch(void* const* d_in, const int* in_sizes, int n_in,
                              void* d_out, int out_size)
{
    const float* x          = (const float*)d_in[0];
    const float* ssm_state  = (const float*)d_in[1];
    const float* conv_state = (const float*)d_in[2];
    const float* w_in       = (const float*)d_in[3];
    const float* conv_w     = (const float*)d_in[4];
    const float* conv_b     = (const float*)d_in[5];
    const float* w_x        = (const float*)d_in[6];
    const float* w_dt       = (const float*)d_in[7];
    const float* b_dt       = (const float*)d_in[8];
    const float* A_log      = (const float*)d_in[9];
    const float* D_skip     = (const float*)d_in[10];
    const float* w_out      = (const float*)d_in[11];
    float* out = (float*)d_out;

    cudaStreamCaptureStatus cs = cudaStreamCaptureStatusNone;
    cudaStreamIsCapturing(cudaStreamLegacy, &cs);
    if (cs == cudaStreamCaptureStatusNone)
        cudaFuncSetAttribute(gemm_mma, cudaFuncAttributeMaxDynamicSharedMemorySize, GEMM_SMEM);

    float *xz, *proj, *projp, *dt;
    __nv_bfloat16 *xs, *wint, *xcs, *wxt, *dtin, *wdtt, *ys, *wott;
    cudaGetSymbolAddress((void**)&xz,    g_xz);
    cudaGetSymbolAddress((void**)&proj,  g_proj);
    cudaGetSymbolAddress((void**)&projp, g_projp);
    cudaGetSymbolAddress((void**)&dt,    g_dt);
    cudaGetSymbolAddress((void**)&xs,    g_xs);
    cudaGetSymbolAddress((void**)&wint,  g_wint);
    cudaGetSymbolAddress((void**)&xcs,   g_xcs);
    cudaGetSymbolAddress((void**)&wxt,   g_wxt);
    cudaGetSymbolAddress((void**)&dtin,  g_dtin);
    cudaGetSymbolAddress((void**)&wdtt,  g_wdtt);
    cudaGetSymbolAddress((void**)&ys,    g_ys);
    cudaGetSymbolAddress((void**)&wott,  g_wott);

    // conversions (3-term split; weights transposed)
    rsplit<<<(ROWS * DIM + 255) / 256, 256>>>(x, DIM, ROWS, DIM, xs);
    tsplit<<<dim3((2 * D_INNER) / 32, DIM / 32), dim3(32, 32)>>>(w_in, DIM, 2 * D_INNER, wint);
    tsplit<<<dim3(3, D_INNER / 32), dim3(32, 32)>>>(w_x, D_INNER, PROJ_N, wxt);
    tsplit<<<dim3(D_INNER / 32, 2), dim3(32, 32)>>>(w_dt, DT_RANK, D_INNER, wdtt);
    tsplit<<<dim3(DIM / 32, D_INNER / 32), dim3(32, 32)>>>(w_out, D_INNER, DIM, wott);

    // 1) xz = x @ w_in   (Kp = 3072)
    gemm_mma<<<dim3(32, 32, 1), 256, GEMM_SMEM>>>(
        xs, 3 * DIM, wint, 3 * DIM, 2 * D_INNER,
        xz, 2 * D_INNER, 3 * DIM, 0, nullptr, 0);

    // 2) depthwise conv + silu (sliding window)
    conv_kernel<<<dim3(D_INNER / 256, T_LEN / CONV_TT, B_SZ), 256>>>(conv_state, conv_w, conv_b);
    convstate_kernel<<<(B_SZ * D_INNER * (D_CONV - 1) + 255) / 256, 256>>>(out + OFF_CONV);

    // 3) proj = x_conv @ w_x  (Kp = 6144, split-K=4 -> 1536 per z)
    gemm_mma<<<dim3(1, 32, KSPLIT), 256, GEMM_SMEM>>>(
        xcs, 3 * D_INNER, wxt, 3 * D_INNER, PROJ_N,
        projp, PROJ_N, (3 * D_INNER) / KSPLIT, (size_t)ROWS * PROJ_N, nullptr, 0);
    reduce_proj<<<(ROWS * PROJ_N + 255) / 256, 256>>>();

    // 4) dt = softplus(proj[:, :64] @ w_dt + b_dt)  (Kp = 192)
    rsplit<<<(ROWS * DT_RANK + 255) / 256, 256>>>(proj, PROJ_N, ROWS, DT_RANK, dtin);
    gemm_mma<<<dim3(16, 32, 1), 256, GEMM_SMEM>>>(
        dtin, 3 * DT_RANK, wdtt, 3 * DT_RANK, D_INNER,
        dt, D_INNER, 3 * DT_RANK, 0, b_dt, 1);

    // 5) selective scan
    scan8<<<(B_SZ * D_INNER * 8) / 256, 256>>>(ssm_state, A_log, D_skip, out + OFF_H);

    // 6) out = y_gated @ w_out  (Kp = 6144)
    gemm_mma<<<dim3(8, 32, 1), 256, GEMM_SMEM>>>(
        ys, 3 * D_INNER, wott, 3 * D_INNER, DIM,
        out, DIM, 3 * D_INNER, 0, nullptr, 0);
}

// round 8
// speedup vs baseline: 2.5747x; 1.0018x over previous
#include <cuda_runtime.h>
#include <cuda_bf16.h>
#include <math.h>
#include <stdint.h>

// Problem constants
#define DIM      1024
#define D_INNER  2048
#define D_STATE  16
#define D_CONV   4
#define DT_RANK  64
#define B_SZ     2
#define T_LEN    2048
#define ROWS     (B_SZ * T_LEN)           // 4096
#define PROJ_N   (DT_RANK + 2 * D_STATE)  // 96
#define KSPLIT   4

// Output offsets (floats): out | h_final | new_conv_state
#define OFF_H    (ROWS * DIM)
#define OFF_CONV (OFF_H + B_SZ * D_INNER * D_STATE)

// ---------------- scratch (device globals) ----------------
__device__ float g_xz[(size_t)ROWS * (2 * D_INNER)];   // x_in | z
__device__ float g_xconv[(size_t)ROWS * D_INNER];
__device__ float g_projp[(size_t)KSPLIT * ROWS * PROJ_N];
__device__ float g_proj[(size_t)ROWS * PROJ_N];
__device__ float g_dt[(size_t)ROWS * D_INNER];
// bf16 3-term split operands (K tripled):
//   A side (activations): [hi | lo | hi]
//   B side (weights):     [hi | hi | lo]
__device__ __align__(16) __nv_bfloat16 g_xs  [(size_t)ROWS * (3 * DIM)];
__device__ __align__(16) __nv_bfloat16 g_wint[(size_t)(2 * D_INNER) * (3 * DIM)];
__device__ __align__(16) __nv_bfloat16 g_xcs [(size_t)ROWS * (3 * D_INNER)];
__device__ __align__(16) __nv_bfloat16 g_wxt [(size_t)PROJ_N * (3 * D_INNER)];
__device__ __align__(16) __nv_bfloat16 g_dtin[(size_t)ROWS * (3 * DT_RANK)];
__device__ __align__(16) __nv_bfloat16 g_wdtt[(size_t)D_INNER * (3 * DT_RANK)];
__device__ __align__(16) __nv_bfloat16 g_ys  [(size_t)ROWS * (3 * D_INNER)];
__device__ __align__(16) __nv_bfloat16 g_wott[(size_t)DIM * (3 * D_INNER)];

// ---------------- mma helpers ----------------
__device__ __forceinline__ uint32_t smem_u32(const void* p) {
    uint32_t a;
    asm("{ .reg .u64 t; cvta.to.shared.u64 t, %1; cvt.u32.u64 %0, t; }" : "=r"(a) : "l"(p));
    return a;
}
__device__ __forceinline__ void ldsm_x4(uint32_t addr, uint32_t& r0, uint32_t& r1,
                                        uint32_t& r2, uint32_t& r3) {
    asm volatile("ldmatrix.sync.aligned.m8n8.x4.shared.b16 {%0,%1,%2,%3}, [%4];"
                 : "=r"(r0), "=r"(r1), "=r"(r2), "=r"(r3) : "r"(addr));
}
__device__ __forceinline__ void mma16816(float* d, const uint32_t* a,
                                         uint32_t b0, uint32_t b1) {
    asm volatile("mma.sync.aligned.m16n8k16.row.col.f32.bf16.bf16.f32 "
                 "{%0,%1,%2,%3}, {%4,%5,%6,%7}, {%8,%9}, {%0,%1,%2,%3};"
                 : "+f"(d[0]), "+f"(d[1]), "+f"(d[2]), "+f"(d[3])
                 : "r"(a[0]), "r"(a[1]), "r"(a[2]), "r"(a[3]), "r"(b0), "r"(b1));
}

// ----------------------------------------------------------------------------
// bf16 HMMA GEMM, cp.async 4-stage + register fragment double-buffering.
// C[M,N] = A[M,Kp] * Bt[N,Kp]^T. Bt row-major [N][ldb] (= B col-major, so the
// MMA B fragment comes from PLAIN ldmatrix, no .trans).
// 128x128 CTA tile, BK=64, 8 warps (4x2), warp tile 32x64 via m16n8k16.
// Split-K via gridDim.z. mode 1: +bias[col] then softplus.
// ----------------------------------------------------------------------------
#define STRIDE  72
#define STAGE_B 18432u                       // 128*72*2 bytes per matrix
#define STAGE_T 36864u                       // A + B per stage
#define STAGES  4
#define GEMM_SMEM (4 * 36864 + 256)

__global__ void __launch_bounds__(256) gemm_mma(
    const __nv_bfloat16* __restrict__ A, int lda,
    const __nv_bfloat16* __restrict__ Bt, int ldb, int N,
    float* __restrict__ C, int ldc, int kLen, size_t zStride,
    const float* __restrict__ bias, int mode)
{
    extern __shared__ char smraw[];
    const uint32_t sb = (smem_u32(smraw) + 127u) & ~127u;

    const int tid = threadIdx.x;
    const int lane = tid & 31;
    const int wid = tid >> 5;
    const int wr = wid >> 1;          // 0..3
    const int wc = wid & 1;           // 0..1
    const int bRow = blockIdx.y << 7;
    const int bCol = blockIdx.x << 7;
    const int kBase = blockIdx.z * kLen;

    const __nv_bfloat16* Ab = A + (size_t)bRow * lda + kBase;

    const int lrow[4] = { (0 * 256 + tid) >> 3, (1 * 256 + tid) >> 3,
                          (2 * 256 + tid) >> 3, (3 * 256 + tid) >> 3 };
    const int lkq = tid & 7;

    float acc[2][8][4];
#pragma unroll
    for (int mi = 0; mi < 2; mi++)
#pragma unroll
        for (int ni = 0; ni < 8; ni++)
#pragma unroll
            for (int e = 0; e < 4; e++) acc[mi][ni][e] = 0.f;

// async copy one 64-K chunk into stage (cidx & 3)
#define S_COPY(cidx)                                                           \
    do {                                                                       \
        const int s_ = (cidx) & (STAGES - 1);                                  \
        const int k0_ = (cidx) << 6;                                           \
        const uint32_t sa_ = sb + (uint32_t)s_ * STAGE_T;                      \
        const uint32_t sb_ = sa_ + STAGE_B;                                    \
        _Pragma("unroll")                                                      \
        for (int i = 0; i < 4; i++) {                                          \
            const uint32_t off = ((uint32_t)lrow[i] * STRIDE + lkq * 8) * 2;   \
            const __nv_bfloat16* ga =                                          \
                Ab + (size_t)lrow[i] * lda + k0_ + lkq * 8;                    \
            asm volatile("cp.async.cg.shared.global [%0], [%1], 16;"           \
                         :: "r"(sa_ + off), "l"(ga));                          \
            const int rbr = bCol + lrow[i];                                    \
            const __nv_bfloat16* gb =                                          \
                Bt + (size_t)(rbr < N ? rbr : N - 1) * ldb + kBase + k0_ + lkq * 8; \
            const uint32_t bsz = (rbr < N) ? 16u : 0u;                         \
            asm volatile("cp.async.cg.shared.global [%0], [%1], 16, %2;"       \
                         :: "r"(sb_ + off), "l"(gb), "r"(bsz));                \
        }                                                                      \
    } while (0)

    const int nchunk = kLen >> 6;
    int cread = 0;
#pragma unroll
    for (int i = 0; i < STAGES - 1; i++) {
        if (cread < nchunk) { S_COPY(cread); cread++; }
        asm volatile("cp.async.commit_group;" ::: "memory");
    }

    // ldmatrix lane address components
    const uint32_t aRow = (uint32_t)(wr * 32 + (lane & 7) + ((lane >> 3) & 1) * 8);
    const uint32_t aKof = (uint32_t)((lane >> 4) * 8);
    const uint32_t bRowL = (uint32_t)(wc * 64 + (lane & 7) + ((lane >> 4) << 3));
    const uint32_t bKof = (uint32_t)(((lane >> 3) & 1) * 8);

    // double-buffered fragments
    uint32_t afr[2][2][4];   // [buf][mi][reg]
    uint32_t bfr[2][8][2];   // [buf][ni][reg]

#define LD_FRAGS(sAs_, sBs_, ks_, buf_)                                        \
    do {                                                                       \
        _Pragma("unroll")                                                      \
        for (int mi = 0; mi < 2; mi++) {                                       \
            uint32_t ad = (sAs_) + ((aRow + mi * 16) * STRIDE + (ks_) * 16 + aKof) * 2; \
            ldsm_x4(ad, afr[buf_][mi][0], afr[buf_][mi][1],                    \
                        afr[buf_][mi][2], afr[buf_][mi][3]);                   \
        }                                                                      \
        _Pragma("unroll")                                                      \
        for (int nq = 0; nq < 4; nq++) {                                       \
            uint32_t bd = (sBs_) + ((bRowL + nq * 16) * STRIDE + (ks_) * 16 + bKof) * 2; \
            ldsm_x4(bd, bfr[buf_][nq * 2][0],     bfr[buf_][nq * 2][1],        \
                        bfr[buf_][nq * 2 + 1][0], bfr[buf_][nq * 2 + 1][1]);   \
        }                                                                      \
    } while (0)

    for (int c = 0; c < nchunk; c++) {
        asm volatile("cp.async.wait_group %0;" :: "n"(STAGES - 2) : "memory");
        __syncthreads();

        const int s = c & (STAGES - 1);
        const uint32_t sAs = sb + (uint32_t)s * STAGE_T;
        const uint32_t sBs = sAs + STAGE_B;

        // issue first fragment loads; their latency hides behind cp.async issue
        LD_FRAGS(sAs, sBs, 0, 0);

        if (cread < nchunk) { S_COPY(cread); cread++; }
        asm volatile("cp.async.commit_group;" ::: "memory");

#pragma unroll
        for (int ks = 0; ks < 4; ks++) {
            const int cur = ks & 1;
            if (ks < 3) LD_FRAGS(sAs, sBs, ks + 1, cur ^ 1);
#pragma unroll
            for (int mi = 0; mi < 2; mi++)
#pragma unroll
                for (int ni = 0; ni < 8; ni++)
                    mma16816(acc[mi][ni], afr[cur][mi],
                             bfr[cur][ni][0], bfr[cur][ni][1]);
        }
    }

    // epilogue
    float* Cz = C + (size_t)blockIdx.z * zStride;
#pragma unroll
    for (int mi = 0; mi < 2; mi++) {
#pragma unroll
        for (int ni = 0; ni < 8; ni++) {
            const int col = bCol + wc * 64 + ni * 8 + (lane & 3) * 2;
            if (col >= N) continue;
            const int r0 = bRow + wr * 32 + mi * 16 + (lane >> 2);
            float v0 = acc[mi][ni][0], v1 = acc[mi][ni][1];
            float v2 = acc[mi][ni][2], v3 = acc[mi][ni][3];
            if (mode == 1) {
                float b0 = bias[col], b1 = bias[col + 1];
                v0 += b0; v1 += b1; v2 += b0; v3 += b1;
                v0 = (v0 > 20.f) ? v0 : log1pf(__expf(v0));
                v1 = (v1 > 20.f) ? v1 : log1pf(__expf(v1));
                v2 = (v2 > 20.f) ? v2 : log1pf(__expf(v2));
                v3 = (v3 > 20.f) ? v3 : log1pf(__expf(v3));
            }
            *(float2*)&Cz[(size_t)r0 * ldc + col] = make_float2(v0, v1);
            *(float2*)&Cz[(size_t)(r0 + 8) * ldc + col] = make_float2(v2, v3);
        }
    }
}

// reduce split-K partials of proj
__global__ void reduce_proj()
{
    int i = blockIdx.x * 256 + threadIdx.x;
    if (i >= ROWS * PROJ_N) return;
    float s = 0.f;
#pragma unroll
    for (int p = 0; p < KSPLIT; p++) s += g_projp[(size_t)p * ROWS * PROJ_N + i];
    g_proj[i] = s;
}

// ---------------- conversion kernels ----------------
// A-side split: in f32 [M][K] (row stride ldin) -> out bf16 [M][3K] = [hi|lo|hi]
__global__ void rsplit(const float* __restrict__ in, int ldin, int M, int K,
                       __nv_bfloat16* __restrict__ out)
{
    int i = blockIdx.x * 256 + threadIdx.x;
    if (i >= M * K) return;
    int m = i / K, k = i - m * K;
    float v = in[(size_t)m * ldin + k];
    __nv_bfloat16 h = __float2bfloat16(v);
    __nv_bfloat16 l = __float2bfloat16(v - __bfloat162float(h));
    size_t base = (size_t)m * (3 * K);
    out[base + k] = h;
    out[base + K + k] = l;
    out[base + 2 * K + k] = h;
}

// B-side transpose + split: in f32 [K][N] -> out bf16 [N][3K] = [hi|hi|lo]
__global__ void tsplit(const float* __restrict__ in, int K, int N,
                       __nv_bfloat16* __restrict__ out)
{
    __shared__ float t[32][33];
    int k0 = blockIdx.y * 32, n0 = blockIdx.x * 32;
    int k = k0 + threadIdx.y, n = n0 + threadIdx.x;
    t[threadIdx.y][threadIdx.x] = (k < K && n < N) ? in[(size_t)k * N + n] : 0.f;
    __syncthreads();
    int on = n0 + threadIdx.y, ok = k0 + threadIdx.x;
    if (on < N && ok < K) {
        float v = t[threadIdx.x][threadIdx.y];
        __nv_bfloat16 h = __float2bfloat16(v);
        __nv_bfloat16 l = __float2bfloat16(v - __bfloat162float(h));
        size_t base = (size_t)on * (3 * K);
        out[base + ok] = h;
        out[base + K + ok] = h;
        out[base + 2 * K + ok] = l;
    }
}

// ---------------- conv + silu: sliding-window, 64 t-steps per thread -------
#define CONV_TT 64
__global__ void __launch_bounds__(256) conv_kernel(
    const float* __restrict__ conv_state,
    const float* __restrict__ conv_w,
    const float* __restrict__ conv_b)
{
    const int d = blockIdx.x * 256 + threadIdx.x;
    const int t0 = blockIdx.y * CONV_TT;
    const int b = blockIdx.z;

    const float w0 = conv_w[d * D_CONV + 0];
    const float w1 = conv_w[d * D_CONV + 1];
    const float w2 = conv_w[d * D_CONV + 2];
    const float w3 = conv_w[d * D_CONV + 3];
    const float cb = conv_b[d];

    const float* xin = g_xz + (size_t)b * T_LEN * (2 * D_INNER) + d;

    float v0, v1, v2;
    if (t0 == 0) {
        v0 = conv_state[((size_t)b * D_INNER + d) * (D_CONV - 1) + 0];
        v1 = conv_state[((size_t)b * D_INNER + d) * (D_CONV - 1) + 1];
        v2 = conv_state[((size_t)b * D_INNER + d) * (D_CONV - 1) + 2];
    } else {
        v0 = xin[(size_t)(t0 - 3) * (2 * D_INNER)];
        v1 = xin[(size_t)(t0 - 2) * (2 * D_INNER)];
        v2 = xin[(size_t)(t0 - 1) * (2 * D_INNER)];
    }

    float* xcv = g_xconv + (size_t)b * T_LEN * D_INNER + d;
    __nv_bfloat16* xcs = g_xcs + (size_t)b * T_LEN * (3 * D_INNER) + d;

#pragma unroll 4
    for (int i = 0; i < CONV_TT; i++) {
        const int t = t0 + i;
        const float xn = xin[(size_t)t * (2 * D_INNER)];
        float acc = cb;
        acc = fmaf(w0, v0, acc);
        acc = fmaf(w1, v1, acc);
        acc = fmaf(w2, v2, acc);
        acc = fmaf(w3, xn, acc);
        const float sig = 1.f / (1.f + __expf(-acc));
        const float r = acc * sig;
        xcv[(size_t)t * D_INNER] = r;
        const __nv_bfloat16 h = __float2bfloat16(r);
        const __nv_bfloat16 l = __float2bfloat16(r - __bfloat162float(h));
        const size_t base = (size_t)t * (3 * D_INNER);
        xcs[base] = h;
        xcs[base + D_INNER] = l;
        xcs[base + 2 * D_INNER] = h;
        v0 = v1; v1 = v2; v2 = xn;
    }
}

__global__ void convstate_kernel(float* __restrict__ outp)
{
    int idx = blockIdx.x * 256 + threadIdx.x;
    if (idx >= B_SZ * D_INNER * (D_CONV - 1)) return;
    int j = idx % (D_CONV - 1);
    int d = (idx / (D_CONV - 1)) % D_INNER;
    int b = idx / (D_INNER * (D_CONV - 1));
    outp[idx] = g_xz[((size_t)b * T_LEN + (T_LEN - (D_CONV - 1) + j)) * (2 * D_INNER) + d];
}

// ---------------- selective scan (emits A-side bf16 split y) ----------------
__global__ void __launch_bounds__(256) scan8(const float* __restrict__ ssm0,
                                             const float* __restrict__ A_log,
                                             const float* __restrict__ D_skip,
                                             float* __restrict__ h_out)
{
    int idx = blockIdx.x * 256 + threadIdx.x;
    int s = idx & 7;
    int d = (idx >> 3) & (D_INNER - 1);
    int b = idx >> 14;
    int n0 = 2 * s;

    float2 hv = *(const float2*)&ssm0[((size_t)b * D_INNER + d) * D_STATE + n0];
    float2 al = *(const float2*)&A_log[d * D_STATE + n0];
    float A0 = -__expf(al.x), A1 = -__expf(al.y);
    float dsk = D_skip[d];

    const float* dt_p = g_dt    + (size_t)b * T_LEN * D_INNER + d;
    const float* xc_p = g_xconv + (size_t)b * T_LEN * D_INNER + d;
    const float* z_p  = g_xz    + (size_t)b * T_LEN * (2 * D_INNER) + D_INNER + d;
    const float* bc_p = g_proj  + (size_t)b * T_LEN * PROJ_N + DT_RANK + n0;
    __nv_bfloat16* ys = g_ys    + (size_t)b * T_LEN * (3 * D_INNER) + d;

    float dt_b[2], xc_b[2], z_b[2];
    float2 B_b[2], C_b[2];
#pragma unroll
    for (int p = 0; p < 2; p++) {
        dt_b[p] = dt_p[(size_t)p * D_INNER];
        xc_b[p] = xc_p[(size_t)p * D_INNER];
        z_b[p]  = z_p[(size_t)p * 2 * D_INNER];
        B_b[p]  = *(const float2*)(bc_p + (size_t)p * PROJ_N);
        C_b[p]  = *(const float2*)(bc_p + (size_t)p * PROJ_N + D_STATE);
    }

    for (int t = 0; t < T_LEN; t++) {
        const int cur = t & 1;
        float dt = dt_b[cur], xc = xc_b[cur], z = z_b[cur];
        float2 Bv = B_b[cur], Cv = C_b[cur];
        if (t + 2 < T_LEN) {
            size_t o = (size_t)(t + 2);
            dt_b[cur] = dt_p[o * D_INNER];
            xc_b[cur] = xc_p[o * D_INNER];
            z_b[cur]  = z_p[o * 2 * D_INNER];
            B_b[cur]  = *(const float2*)(bc_p + o * PROJ_N);
            C_b[cur]  = *(const float2*)(bc_p + o * PROJ_N + D_STATE);
        }
        float e0 = __expf(dt * A0);
        float e1 = __expf(dt * A1);
        float dx = dt * xc;
        hv.x = fmaf(e0, hv.x, dx * Bv.x);
        hv.y = fmaf(e1, hv.y, dx * Bv.y);
        float r = fmaf(hv.x, Cv.x, hv.y * Cv.y);
        r += __shfl_xor_sync(0xffffffffu, r, 1, 8);
        r += __shfl_xor_sync(0xffffffffu, r, 2, 8);
        r += __shfl_xor_sync(0xffffffffu, r, 4, 8);
        if (s == 0) {
            float yv = fmaf(dsk, xc, r);
            float sz = z / (1.f + __expf(-z));
            yv *= sz;
            __nv_bfloat16 h = __float2bfloat16(yv);
            __nv_bfloat16 l = __float2bfloat16(yv - __bfloat162float(h));
            size_t base = (size_t)t * (3 * D_INNER);
            ys[base] = h;
            ys[base + D_INNER] = l;
            ys[base + 2 * D_INNER] = h;
        }
    }
    *(float2*)&h_out[((size_t)b * D_INNER + d) * D_STATE + n0] = hv;
}

// ----------------------------------------------------------------------------
extern "C" void kernel_launch(void* const* d_in, const int* in_sizes, int n_in,
                              void* d_out, int out_size)
{
    const float* x          = (const float*)d_in[0];
    const float* ssm_state  = (const float*)d_in[1];
    const float* conv_state = (const float*)d_in[2];
    const float* w_in       = (const float*)d_in[3];
    const float* conv_w     = (const float*)d_in[4];
    const float* conv_b     = (const float*)d_in[5];
    const float* w_x        = (const float*)d_in[6];
    const float* w_dt       = (const float*)d_in[7];
    const float* b_dt       = (const float*)d_in[8];
    const float* A_log      = (const float*)d_in[9];
    const float* D_skip     = (const float*)d_in[10];
    const float* w_out      = (const float*)d_in[11];
    float* out = (float*)d_out;

    cudaStreamCaptureStatus cs = cudaStreamCaptureStatusNone;
    cudaStreamIsCapturing(cudaStreamLegacy, &cs);
    if (cs == cudaStreamCaptureStatusNone)
        cudaFuncSetAttribute(gemm_mma, cudaFuncAttributeMaxDynamicSharedMemorySize, GEMM_SMEM);

    float *xz, *proj, *projp, *dt;
    __nv_bfloat16 *xs, *wint, *xcs, *wxt, *dtin, *wdtt, *ys, *wott;
    cudaGetSymbolAddress((void**)&xz,    g_xz);
    cudaGetSymbolAddress((void**)&proj,  g_proj);
    cudaGetSymbolAddress((void**)&projp, g_projp);
    cudaGetSymbolAddress((void**)&dt,    g_dt);
    cudaGetSymbolAddress((void**)&xs,    g_xs);
    cudaGetSymbolAddress((void**)&wint,  g_wint);
    cudaGetSymbolAddress((void**)&xcs,   g_xcs);
    cudaGetSymbolAddress((void**)&wxt,   g_wxt);
    cudaGetSymbolAddress((void**)&dtin,  g_dtin);
    cudaGetSymbolAddress((void**)&wdtt,  g_wdtt);
    cudaGetSymbolAddress((void**)&ys,    g_ys);
    cudaGetSymbolAddress((void**)&wott,  g_wott);

    // conversions (3-term split; weights transposed)
    rsplit<<<(ROWS * DIM + 255) / 256, 256>>>(x, DIM, ROWS, DIM, xs);
    tsplit<<<dim3((2 * D_INNER) / 32, DIM / 32), dim3(32, 32)>>>(w_in, DIM, 2 * D_INNER, wint);
    tsplit<<<dim3(3, D_INNER / 32), dim3(32, 32)>>>(w_x, D_INNER, PROJ_N, wxt);
    tsplit<<<dim3(D_INNER / 32, 2), dim3(32, 32)>>>(w_dt, DT_RANK, D_INNER, wdtt);
    tsplit<<<dim3(DIM / 32, D_INNER / 32), dim3(32, 32)>>>(w_out, D_INNER, DIM, wott);

    // 1) xz = x @ w_in   (Kp = 3072)
    gemm_mma<<<dim3(32, 32, 1), 256, GEMM_SMEM>>>(
        xs, 3 * DIM, wint, 3 * DIM, 2 * D_INNER,
        xz, 2 * D_INNER, 3 * DIM, 0, nullptr, 0);

    // 2) depthwise conv + silu (sliding window)
    conv_kernel<<<dim3(D_INNER / 256, T_LEN / CONV_TT, B_SZ), 256>>>(conv_state, conv_w, conv_b);
    convstate_kernel<<<(B_SZ * D_INNER * (D_CONV - 1) + 255) / 256, 256>>>(out + OFF_CONV);

    // 3) proj = x_conv @ w_x  (Kp = 6144, split-K=4 -> 1536 per z)
    gemm_mma<<<dim3(1, 32, KSPLIT), 256, GEMM_SMEM>>>(
        xcs, 3 * D_INNER, wxt, 3 * D_INNER, PROJ_N,
        projp, PROJ_N, (3 * D_INNER) / KSPLIT, (size_t)ROWS * PROJ_N, nullptr, 0);
    reduce_proj<<<(ROWS * PROJ_N + 255) / 256, 256>>>();

    // 4) dt = softplus(proj[:, :64] @ w_dt + b_dt)  (Kp = 192)
    rsplit<<<(ROWS * DT_RANK + 255) / 256, 256>>>(proj, PROJ_N, ROWS, DT_RANK, dtin);
    gemm_mma<<<dim3(16, 32, 1), 256, GEMM_SMEM>>>(
        dtin, 3 * DT_RANK, wdtt, 3 * DT_RANK, D_INNER,
        dt, D_INNER, 3 * DT_RANK, 0, b_dt, 1);

    // 5) selective scan
    scan8<<<(B_SZ * D_INNER * 8) / 256, 256>>>(ssm_state, A_log, D_skip, out + OFF_H);

    // 6) out = y_gated @ w_out  (Kp = 6144)
    gemm_mma<<<dim3(8, 32, 1), 256, GEMM_SMEM>>>(
        ys, 3 * D_INNER, wott, 3 * D_INNER, DIM,
        out, DIM, 3 * D_INNER, 0, nullptr, 0);
}

// round 9
// speedup vs baseline: 2.7014x; 1.0492x over previous
#include <cuda_runtime.h>
#include <cuda_bf16.h>
#include <math.h>
#include <stdint.h>

// Problem constants
#define DIM      1024
#define D_INNER  2048
#define D_STATE  16
#define D_CONV   4
#define DT_RANK  64
#define B_SZ     2
#define T_LEN    2048
#define ROWS     (B_SZ * T_LEN)           // 4096
#define PROJ_N   (DT_RANK + 2 * D_STATE)  // 96
#define KSPLIT   4

// Output offsets (floats): out | h_final | new_conv_state
#define OFF_H    (ROWS * DIM)
#define OFF_CONV (OFF_H + B_SZ * D_INNER * D_STATE)

// ---------------- scratch (device globals) ----------------
__device__ float g_xz[(size_t)ROWS * (2 * D_INNER)];   // x_in | z
__device__ float g_xconv[(size_t)ROWS * D_INNER];
__device__ float g_projp[(size_t)KSPLIT * ROWS * PROJ_N];
__device__ float g_proj[(size_t)ROWS * PROJ_N];
__device__ float g_dt[(size_t)ROWS * D_INNER];
// bf16 3-term split operands (K tripled):
//   A side (activations): [hi | lo | hi]
//   B side (weights):     [hi | hi | lo]
__device__ __align__(16) __nv_bfloat16 g_xs  [(size_t)ROWS * (3 * DIM)];
__device__ __align__(16) __nv_bfloat16 g_wint[(size_t)(2 * D_INNER) * (3 * DIM)];
__device__ __align__(16) __nv_bfloat16 g_xcs [(size_t)ROWS * (3 * D_INNER)];
__device__ __align__(16) __nv_bfloat16 g_wxt [(size_t)PROJ_N * (3 * D_INNER)];
__device__ __align__(16) __nv_bfloat16 g_dtin[(size_t)ROWS * (3 * DT_RANK)];
__device__ __align__(16) __nv_bfloat16 g_wdtt[(size_t)D_INNER * (3 * DT_RANK)];
__device__ __align__(16) __nv_bfloat16 g_ys  [(size_t)ROWS * (3 * D_INNER)];
__device__ __align__(16) __nv_bfloat16 g_wott[(size_t)DIM * (3 * D_INNER)];

// ---------------- mma helpers ----------------
__device__ __forceinline__ uint32_t smem_u32(const void* p) {
    uint32_t a;
    asm("{ .reg .u64 t; cvta.to.shared.u64 t, %1; cvt.u32.u64 %0, t; }" : "=r"(a) : "l"(p));
    return a;
}
__device__ __forceinline__ void ldsm_x4(uint32_t addr, uint32_t& r0, uint32_t& r1,
                                        uint32_t& r2, uint32_t& r3) {
    asm volatile("ldmatrix.sync.aligned.m8n8.x4.shared.b16 {%0,%1,%2,%3}, [%4];"
                 : "=r"(r0), "=r"(r1), "=r"(r2), "=r"(r3) : "r"(addr));
}
__device__ __forceinline__ void mma16816(float* d, const uint32_t* a,
                                         uint32_t b0, uint32_t b1) {
    asm volatile("mma.sync.aligned.m16n8k16.row.col.f32.bf16.bf16.f32 "
                 "{%0,%1,%2,%3}, {%4,%5,%6,%7}, {%8,%9}, {%0,%1,%2,%3};"
                 : "+f"(d[0]), "+f"(d[1]), "+f"(d[2]), "+f"(d[3])
                 : "r"(a[0]), "r"(a[1]), "r"(a[2]), "r"(a[3]), "r"(b0), "r"(b1));
}

// ----------------------------------------------------------------------------
// bf16 HMMA GEMM, cp.async 3-stage, 2 CTAs/SM (4 warps/SMSP).
// C[M,N] = A[M,Kp] * Bt[N,Kp]^T. Bt row-major [N][ldb] (= B col-major, so the
// MMA B fragment comes from PLAIN ldmatrix, no .trans).
// 128x128 CTA tile, BK=64, 8 warps (4x2), warp tile 32x64 via m16n8k16.
// Split-K via gridDim.z. mode 1: +bias[col] then softplus.
// ----------------------------------------------------------------------------
#define STRIDE  72
#define STAGE_B 18432u                       // 128*72*2 bytes per matrix
#define STAGE_T 36864u                       // A + B per stage
#define STAGES  3
#define GEMM_SMEM (STAGES * 36864 + 256)

__global__ void __launch_bounds__(256, 2) gemm_mma(
    const __nv_bfloat16* __restrict__ A, int lda,
    const __nv_bfloat16* __restrict__ Bt, int ldb, int N,
    float* __restrict__ C, int ldc, int kLen, size_t zStride,
    const float* __restrict__ bias, int mode)
{
    extern __shared__ char smraw[];
    const uint32_t sb = (smem_u32(smraw) + 127u) & ~127u;

    const int tid = threadIdx.x;
    const int lane = tid & 31;
    const int wid = tid >> 5;
    const int wr = wid >> 1;          // 0..3
    const int wc = wid & 1;           // 0..1
    const int bRow = blockIdx.y << 7;
    const int bCol = blockIdx.x << 7;
    const int kBase = blockIdx.z * kLen;

    const __nv_bfloat16* Ab = A + (size_t)bRow * lda + kBase;

    const int lrow[4] = { (0 * 256 + tid) >> 3, (1 * 256 + tid) >> 3,
                          (2 * 256 + tid) >> 3, (3 * 256 + tid) >> 3 };
    const int lkq = tid & 7;

    float acc[2][8][4];
#pragma unroll
    for (int mi = 0; mi < 2; mi++)
#pragma unroll
        for (int ni = 0; ni < 8; ni++)
#pragma unroll
            for (int e = 0; e < 4; e++) acc[mi][ni][e] = 0.f;

// async copy one 64-K chunk into stage (cidx % STAGES)
#define S_COPY(cidx)                                                           \
    do {                                                                       \
        const int s_ = (cidx) % STAGES;                                        \
        const int k0_ = (cidx) << 6;                                           \
        const uint32_t sa_ = sb + (uint32_t)s_ * STAGE_T;                      \
        const uint32_t sb_ = sa_ + STAGE_B;                                    \
        _Pragma("unroll")                                                      \
        for (int i = 0; i < 4; i++) {                                          \
            const uint32_t off = ((uint32_t)lrow[i] * STRIDE + lkq * 8) * 2;   \
            const __nv_bfloat16* ga =                                          \
                Ab + (size_t)lrow[i] * lda + k0_ + lkq * 8;                    \
            asm volatile("cp.async.cg.shared.global [%0], [%1], 16;"           \
                         :: "r"(sa_ + off), "l"(ga));                          \
            const int rbr = bCol + lrow[i];                                    \
            const __nv_bfloat16* gb =                                          \
                Bt + (size_t)(rbr < N ? rbr : N - 1) * ldb + kBase + k0_ + lkq * 8; \
            const uint32_t bsz = (rbr < N) ? 16u : 0u;                         \
            asm volatile("cp.async.cg.shared.global [%0], [%1], 16, %2;"       \
                         :: "r"(sb_ + off), "l"(gb), "r"(bsz));                \
        }                                                                      \
    } while (0)

    const int nchunk = kLen >> 6;
    int cread = 0;
#pragma unroll
    for (int i = 0; i < STAGES - 1; i++) {
        if (cread < nchunk) { S_COPY(cread); cread++; }
        asm volatile("cp.async.commit_group;" ::: "memory");
    }

    // ldmatrix lane address components
    const uint32_t aRow = (uint32_t)(wr * 32 + (lane & 7) + ((lane >> 3) & 1) * 8);
    const uint32_t aKof = (uint32_t)((lane >> 4) * 8);
    const uint32_t bRowL = (uint32_t)(wc * 64 + (lane & 7) + ((lane >> 4) << 3));
    const uint32_t bKof = (uint32_t)(((lane >> 3) & 1) * 8);

    for (int c = 0; c < nchunk; c++) {
        asm volatile("cp.async.wait_group %0;" :: "n"(STAGES - 2) : "memory");
        __syncthreads();

        if (cread < nchunk) { S_COPY(cread); cread++; }
        asm volatile("cp.async.commit_group;" ::: "memory");

        const int s = c % STAGES;
        const uint32_t sAs = sb + (uint32_t)s * STAGE_T;
        const uint32_t sBs = sAs + STAGE_B;

#pragma unroll
        for (int ks = 0; ks < 4; ks++) {
            uint32_t afr[2][4];
#pragma unroll
            for (int mi = 0; mi < 2; mi++) {
                uint32_t ad = sAs + ((aRow + mi * 16) * STRIDE + ks * 16 + aKof) * 2;
                ldsm_x4(ad, afr[mi][0], afr[mi][1], afr[mi][2], afr[mi][3]);
            }
            uint32_t bfr[8][2];
#pragma unroll
            for (int nq = 0; nq < 4; nq++) {
                uint32_t bd = sBs + ((bRowL + nq * 16) * STRIDE + ks * 16 + bKof) * 2;
                uint32_t r0, r1, r2, r3;
                ldsm_x4(bd, r0, r1, r2, r3);   // non-trans: Bt rows ARE col-major B
                bfr[nq * 2][0] = r0; bfr[nq * 2][1] = r1;
                bfr[nq * 2 + 1][0] = r2; bfr[nq * 2 + 1][1] = r3;
            }
#pragma unroll
            for (int mi = 0; mi < 2; mi++)
#pragma unroll
                for (int ni = 0; ni < 8; ni++)
                    mma16816(acc[mi][ni], afr[mi], bfr[ni][0], bfr[ni][1]);
        }
    }

    // epilogue
    float* Cz = C + (size_t)blockIdx.z * zStride;
#pragma unroll
    for (int mi = 0; mi < 2; mi++) {
#pragma unroll
        for (int ni = 0; ni < 8; ni++) {
            const int col = bCol + wc * 64 + ni * 8 + (lane & 3) * 2;
            if (col >= N) continue;
            const int r0 = bRow + wr * 32 + mi * 16 + (lane >> 2);
            float v0 = acc[mi][ni][0], v1 = acc[mi][ni][1];
            float v2 = acc[mi][ni][2], v3 = acc[mi][ni][3];
            if (mode == 1) {
                float b0 = bias[col], b1 = bias[col + 1];
                v0 += b0; v1 += b1; v2 += b0; v3 += b1;
                v0 = (v0 > 20.f) ? v0 : log1pf(__expf(v0));
                v1 = (v1 > 20.f) ? v1 : log1pf(__expf(v1));
                v2 = (v2 > 20.f) ? v2 : log1pf(__expf(v2));
                v3 = (v3 > 20.f) ? v3 : log1pf(__expf(v3));
            }
            *(float2*)&Cz[(size_t)r0 * ldc + col] = make_float2(v0, v1);
            *(float2*)&Cz[(size_t)(r0 + 8) * ldc + col] = make_float2(v2, v3);
        }
    }
}

// reduce split-K partials of proj
__global__ void reduce_proj()
{
    int i = blockIdx.x * 256 + threadIdx.x;
    if (i >= ROWS * PROJ_N) return;
    float s = 0.f;
#pragma unroll
    for (int p = 0; p < KSPLIT; p++) s += g_projp[(size_t)p * ROWS * PROJ_N + i];
    g_proj[i] = s;
}

// ---------------- conversion kernels ----------------
// A-side split: in f32 [M][K] (row stride ldin) -> out bf16 [M][3K] = [hi|lo|hi]
__global__ void rsplit(const float* __restrict__ in, int ldin, int M, int K,
                       __nv_bfloat16* __restrict__ out)
{
    int i = blockIdx.x * 256 + threadIdx.x;
    if (i >= M * K) return;
    int m = i / K, k = i - m * K;
    float v = in[(size_t)m * ldin + k];
    __nv_bfloat16 h = __float2bfloat16(v);
    __nv_bfloat16 l = __float2bfloat16(v - __bfloat162float(h));
    size_t base = (size_t)m * (3 * K);
    out[base + k] = h;
    out[base + K + k] = l;
    out[base + 2 * K + k] = h;
}

// B-side transpose + split: in f32 [K][N] -> out bf16 [N][3K] = [hi|hi|lo]
__global__ void tsplit(const float* __restrict__ in, int K, int N,
                       __nv_bfloat16* __restrict__ out)
{
    __shared__ float t[32][33];
    int k0 = blockIdx.y * 32, n0 = blockIdx.x * 32;
    int k = k0 + threadIdx.y, n = n0 + threadIdx.x;
    t[threadIdx.y][threadIdx.x] = (k < K && n < N) ? in[(size_t)k * N + n] : 0.f;
    __syncthreads();
    int on = n0 + threadIdx.y, ok = k0 + threadIdx.x;
    if (on < N && ok < K) {
        float v = t[threadIdx.x][threadIdx.y];
        __nv_bfloat16 h = __float2bfloat16(v);
        __nv_bfloat16 l = __float2bfloat16(v - __bfloat162float(h));
        size_t base = (size_t)on * (3 * K);
        out[base + ok] = h;
        out[base + K + ok] = h;
        out[base + 2 * K + ok] = l;
    }
}

// ---------------- conv + silu: sliding-window, 64 t-steps per thread -------
#define CONV_TT 64
__global__ void __launch_bounds__(256) conv_kernel(
    const float* __restrict__ conv_state,
    const float* __restrict__ conv_w,
    const float* __restrict__ conv_b)
{
    const int d = blockIdx.x * 256 + threadIdx.x;
    const int t0 = blockIdx.y * CONV_TT;
    const int b = blockIdx.z;

    const float w0 = conv_w[d * D_CONV + 0];
    const float w1 = conv_w[d * D_CONV + 1];
    const float w2 = conv_w[d * D_CONV + 2];
    const float w3 = conv_w[d * D_CONV + 3];
    const float cb = conv_b[d];

    const float* xin = g_xz + (size_t)b * T_LEN * (2 * D_INNER) + d;

    float v0, v1, v2;
    if (t0 == 0) {
        v0 = conv_state[((size_t)b * D_INNER + d) * (D_CONV - 1) + 0];
        v1 = conv_state[((size_t)b * D_INNER + d) * (D_CONV - 1) + 1];
        v2 = conv_state[((size_t)b * D_INNER + d) * (D_CONV - 1) + 2];
    } else {
        v0 = xin[(size_t)(t0 - 3) * (2 * D_INNER)];
        v1 = xin[(size_t)(t0 - 2) * (2 * D_INNER)];
        v2 = xin[(size_t)(t0 - 1) * (2 * D_INNER)];
    }

    float* xcv = g_xconv + (size_t)b * T_LEN * D_INNER + d;
    __nv_bfloat16* xcs = g_xcs + (size_t)b * T_LEN * (3 * D_INNER) + d;

#pragma unroll 4
    for (int i = 0; i < CONV_TT; i++) {
        const int t = t0 + i;
        const float xn = xin[(size_t)t * (2 * D_INNER)];
        float acc = cb;
        acc = fmaf(w0, v0, acc);
        acc = fmaf(w1, v1, acc);
        acc = fmaf(w2, v2, acc);
        acc = fmaf(w3, xn, acc);
        const float sig = 1.f / (1.f + __expf(-acc));
        const float r = acc * sig;
        xcv[(size_t)t * D_INNER] = r;
        const __nv_bfloat16 h = __float2bfloat16(r);
        const __nv_bfloat16 l = __float2bfloat16(r - __bfloat162float(h));
        const size_t base = (size_t)t * (3 * D_INNER);
        xcs[base] = h;
        xcs[base + D_INNER] = l;
        xcs[base + 2 * D_INNER] = h;
        v0 = v1; v1 = v2; v2 = xn;
    }
}

__global__ void convstate_kernel(float* __restrict__ outp)
{
    int idx = blockIdx.x * 256 + threadIdx.x;
    if (idx >= B_SZ * D_INNER * (D_CONV - 1)) return;
    int j = idx % (D_CONV - 1);
    int d = (idx / (D_CONV - 1)) % D_INNER;
    int b = idx / (D_INNER * (D_CONV - 1));
    outp[idx] = g_xz[((size_t)b * T_LEN + (T_LEN - (D_CONV - 1) + j)) * (2 * D_INNER) + d];
}

// ---------------- selective scan (emits A-side bf16 split y) ----------------
__global__ void __launch_bounds__(256) scan8(const float* __restrict__ ssm0,
                                             const float* __restrict__ A_log,
                                             const float* __restrict__ D_skip,
                                             float* __restrict__ h_out)
{
    int idx = blockIdx.x * 256 + threadIdx.x;
    int s = idx & 7;
    int d = (idx >> 3) & (D_INNER - 1);
    int b = idx >> 14;
    int n0 = 2 * s;

    float2 hv = *(const float2*)&ssm0[((size_t)b * D_INNER + d) * D_STATE + n0];
    float2 al = *(const float2*)&A_log[d * D_STATE + n0];
    float A0 = -__expf(al.x), A1 = -__expf(al.y);
    float dsk = D_skip[d];

    const float* dt_p = g_dt    + (size_t)b * T_LEN * D_INNER + d;
    const float* xc_p = g_xconv + (size_t)b * T_LEN * D_INNER + d;
    const float* z_p  = g_xz    + (size_t)b * T_LEN * (2 * D_INNER) + D_INNER + d;
    const float* bc_p = g_proj  + (size_t)b * T_LEN * PROJ_N + DT_RANK + n0;
    __nv_bfloat16* ys = g_ys    + (size_t)b * T_LEN * (3 * D_INNER) + d;

    float dt_b[2], xc_b[2], z_b[2];
    float2 B_b[2], C_b[2];
#pragma unroll
    for (int p = 0; p < 2; p++) {
        dt_b[p] = dt_p[(size_t)p * D_INNER];
        xc_b[p] = xc_p[(size_t)p * D_INNER];
        z_b[p]  = z_p[(size_t)p * 2 * D_INNER];
        B_b[p]  = *(const float2*)(bc_p + (size_t)p * PROJ_N);
        C_b[p]  = *(const float2*)(bc_p + (size_t)p * PROJ_N + D_STATE);
    }

    for (int t = 0; t < T_LEN; t++) {
        const int cur = t & 1;
        float dt = dt_b[cur], xc = xc_b[cur], z = z_b[cur];
        float2 Bv = B_b[cur], Cv = C_b[cur];
        if (t + 2 < T_LEN) {
            size_t o = (size_t)(t + 2);
            dt_b[cur] = dt_p[o * D_INNER];
            xc_b[cur] = xc_p[o * D_INNER];
            z_b[cur]  = z_p[o * 2 * D_INNER];
            B_b[cur]  = *(const float2*)(bc_p + o * PROJ_N);
            C_b[cur]  = *(const float2*)(bc_p + o * PROJ_N + D_STATE);
        }
        float e0 = __expf(dt * A0);
        float e1 = __expf(dt * A1);
        float dx = dt * xc;
        hv.x = fmaf(e0, hv.x, dx * Bv.x);
        hv.y = fmaf(e1, hv.y, dx * Bv.y);
        float r = fmaf(hv.x, Cv.x, hv.y * Cv.y);
        r += __shfl_xor_sync(0xffffffffu, r, 1, 8);
        r += __shfl_xor_sync(0xffffffffu, r, 2, 8);
        r += __shfl_xor_sync(0xffffffffu, r, 4, 8);
        if (s == 0) {
            float yv = fmaf(dsk, xc, r);
            float sz = z / (1.f + __expf(-z));
            yv *= sz;
            __nv_bfloat16 h = __float2bfloat16(yv);
            __nv_bfloat16 l = __float2bfloat16(yv - __bfloat162float(h));
            size_t base = (size_t)t * (3 * D_INNER);
            ys[base] = h;
            ys[base + D_INNER] = l;
            ys[base + 2 * D_INNER] = h;
        }
    }
    *(float2*)&h_out[((size_t)b * D_INNER + d) * D_STATE + n0] = hv;
}

// ----------------------------------------------------------------------------
extern "C" void kernel_launch(void* const* d_in, const int* in_sizes, int n_in,
                              void* d_out, int out_size)
{
    const float* x          = (const float*)d_in[0];
    const float* ssm_state  = (const float*)d_in[1];
    const float* conv_state = (const float*)d_in[2];
    const float* w_in       = (const float*)d_in[3];
    const float* conv_w     = (const float*)d_in[4];
    const float* conv_b     = (const float*)d_in[5];
    const float* w_x        = (const float*)d_in[6];
    const float* w_dt       = (const float*)d_in[7];
    const float* b_dt       = (const float*)d_in[8];
    const float* A_log      = (const float*)d_in[9];
    const float* D_skip     = (const float*)d_in[10];
    const float* w_out      = (const float*)d_in[11];
    float* out = (float*)d_out;

    cudaStreamCaptureStatus cs = cudaStreamCaptureStatusNone;
    cudaStreamIsCapturing(cudaStreamLegacy, &cs);
    if (cs == cudaStreamCaptureStatusNone)
        cudaFuncSetAttribute(gemm_mma, cudaFuncAttributeMaxDynamicSharedMemorySize, GEMM_SMEM);

    float *xz, *proj, *projp, *dt;
    __nv_bfloat16 *xs, *wint, *xcs, *wxt, *dtin, *wdtt, *ys, *wott;
    cudaGetSymbolAddress((void**)&xz,    g_xz);
    cudaGetSymbolAddress((void**)&proj,  g_proj);
    cudaGetSymbolAddress((void**)&projp, g_projp);
    cudaGetSymbolAddress((void**)&dt,    g_dt);
    cudaGetSymbolAddress((void**)&xs,    g_xs);
    cudaGetSymbolAddress((void**)&wint,  g_wint);
    cudaGetSymbolAddress((void**)&xcs,   g_xcs);
    cudaGetSymbolAddress((void**)&wxt,   g_wxt);
    cudaGetSymbolAddress((void**)&dtin,  g_dtin);
    cudaGetSymbolAddress((void**)&wdtt,  g_wdtt);
    cudaGetSymbolAddress((void**)&ys,    g_ys);
    cudaGetSymbolAddress((void**)&wott,  g_wott);

    // Launch order chosen so gemm1 is the 4th launch (ncu capture slot).
    rsplit<<<(ROWS * DIM + 255) / 256, 256>>>(x, DIM, ROWS, DIM, xs);          // 1
    tsplit<<<dim3((2 * D_INNER) / 32, DIM / 32), dim3(32, 32)>>>(w_in, DIM, 2 * D_INNER, wint); // 2
    tsplit<<<dim3(DIM / 32, D_INNER / 32), dim3(32, 32)>>>(w_out, D_INNER, DIM, wott);          // 3

    // 4) xz = x @ w_in   (Kp = 3072)  <-- profiled launch
    gemm_mma<<<dim3(32, 32, 1), 256, GEMM_SMEM>>>(
        xs, 3 * DIM, wint, 3 * DIM, 2 * D_INNER,
        xz, 2 * D_INNER, 3 * DIM, 0, nullptr, 0);

    // 5) depthwise conv + silu
    conv_kernel<<<dim3(D_INNER / 256, T_LEN / CONV_TT, B_SZ), 256>>>(conv_state, conv_w, conv_b);
    // 6) new conv state
    convstate_kernel<<<(B_SZ * D_INNER * (D_CONV - 1) + 255) / 256, 256>>>(out + OFF_CONV);
    // 7)
    tsplit<<<dim3(3, D_INNER / 32), dim3(32, 32)>>>(w_x, D_INNER, PROJ_N, wxt);

    // 8) proj = x_conv @ w_x  (Kp = 6144, split-K=4 -> 1536 per z)
    gemm_mma<<<dim3(1, 32, KSPLIT), 256, GEMM_SMEM>>>(
        xcs, 3 * D_INNER, wxt, 3 * D_INNER, PROJ_N,
        projp, PROJ_N, (3 * D_INNER) / KSPLIT, (size_t)ROWS * PROJ_N, nullptr, 0);
    // 9)
    reduce_proj<<<(ROWS * PROJ_N + 255) / 256, 256>>>();

    // 10-11) dt inputs
    rsplit<<<(ROWS * DT_RANK + 255) / 256, 256>>>(proj, PROJ_N, ROWS, DT_RANK, dtin);
    tsplit<<<dim3(D_INNER / 32, 2), dim3(32, 32)>>>(w_dt, DT_RANK, D_INNER, wdtt);

    // 12) dt = softplus(proj[:, :64] @ w_dt + b_dt)  (Kp = 192)
    gemm_mma<<<dim3(16, 32, 1), 256, GEMM_SMEM>>>(
        dtin, 3 * DT_RANK, wdtt, 3 * DT_RANK, D_INNER,
        dt, D_INNER, 3 * DT_RANK, 0, b_dt, 1);

    // 13) selective scan
    scan8<<<(B_SZ * D_INNER * 8) / 256, 256>>>(ssm_state, A_log, D_skip, out + OFF_H);

    // 14) out = y_gated @ w_out  (Kp = 6144)
    gemm_mma<<<dim3(8, 32, 1), 256, GEMM_SMEM>>>(
        ys, 3 * D_INNER, wott, 3 * D_INNER, DIM,
        out, DIM, 3 * D_INNER, 0, nullptr, 0);
}

// round 10
// speedup vs baseline: 3.0795x; 1.1399x over previous
#include <cuda_runtime.h>
#include <cuda_fp16.h>
#include <math.h>
#include <stdint.h>

// Problem constants
#define DIM      1024
#define D_INNER  2048
#define D_STATE  16
#define D_CONV   4
#define DT_RANK  64
#define B_SZ     2
#define T_LEN    2048
#define ROWS     (B_SZ * T_LEN)           // 4096
#define PROJ_N   (DT_RANK + 2 * D_STATE)  // 96
#define KSPLIT   4

// Output offsets (floats): out | h_final | new_conv_state
#define OFF_H    (ROWS * DIM)
#define OFF_CONV (OFF_H + B_SZ * D_INNER * D_STATE)

// ---------------- scratch (device globals) ----------------
__device__ float g_xz[(size_t)ROWS * (2 * D_INNER)];   // x_in | z
__device__ float g_xconv[(size_t)ROWS * D_INNER];
__device__ float g_projp[(size_t)KSPLIT * ROWS * PROJ_N];
__device__ float g_proj[(size_t)ROWS * PROJ_N];
__device__ float g_dt[(size_t)ROWS * D_INNER];
// fp16 2-term split operands (K doubled):
//   A side (activations): [hi | lo]
//   B side (weights):     [hi | hi]   (dropped term a_hi*b_lo ~ 2^-12)
__device__ __align__(16) __half g_xs  [(size_t)ROWS * (2 * DIM)];
__device__ __align__(16) __half g_wint[(size_t)(2 * D_INNER) * (2 * DIM)];
__device__ __align__(16) __half g_xcs [(size_t)ROWS * (2 * D_INNER)];
__device__ __align__(16) __half g_wxt [(size_t)PROJ_N * (2 * D_INNER)];
__device__ __align__(16) __half g_dtin[(size_t)ROWS * (2 * DT_RANK)];
__device__ __align__(16) __half g_wdtt[(size_t)D_INNER * (2 * DT_RANK)];
__device__ __align__(16) __half g_ys  [(size_t)ROWS * (2 * D_INNER)];
__device__ __align__(16) __half g_wott[(size_t)DIM * (2 * D_INNER)];

// ---------------- mma helpers ----------------
__device__ __forceinline__ uint32_t smem_u32(const void* p) {
    uint32_t a;
    asm("{ .reg .u64 t; cvta.to.shared.u64 t, %1; cvt.u32.u64 %0, t; }" : "=r"(a) : "l"(p));
    return a;
}
__device__ __forceinline__ void ldsm_x4(uint32_t addr, uint32_t& r0, uint32_t& r1,
                                        uint32_t& r2, uint32_t& r3) {
    asm volatile("ldmatrix.sync.aligned.m8n8.x4.shared.b16 {%0,%1,%2,%3}, [%4];"
                 : "=r"(r0), "=r"(r1), "=r"(r2), "=r"(r3) : "r"(addr));
}
__device__ __forceinline__ void mma16816(float* d, const uint32_t* a,
                                         uint32_t b0, uint32_t b1) {
    asm volatile("mma.sync.aligned.m16n8k16.row.col.f32.f16.f16.f32 "
                 "{%0,%1,%2,%3}, {%4,%5,%6,%7}, {%8,%9}, {%0,%1,%2,%3};"
                 : "+f"(d[0]), "+f"(d[1]), "+f"(d[2]), "+f"(d[3])
                 : "r"(a[0]), "r"(a[1]), "r"(a[2]), "r"(a[3]), "r"(b0), "r"(b1));
}

// ----------------------------------------------------------------------------
// fp16 HMMA GEMM, cp.async 3-stage, 2 CTAs/SM (4 warps/SMSP).
// C[M,N] = A[M,Kp] * Bt[N,Kp]^T. Bt row-major [N][ldb] (= B col-major, so the
// MMA B fragment comes from PLAIN ldmatrix, no .trans).
// 128x128 CTA tile, BK=64, 8 warps (4x2), warp tile 32x64 via m16n8k16.
// Split-K via gridDim.z. mode 1: +bias[col] then softplus.
// ----------------------------------------------------------------------------
#define STRIDE  72
#define STAGE_B 18432u                       // 128*72*2 bytes per matrix
#define STAGE_T 36864u                       // A + B per stage
#define STAGES  3
#define GEMM_SMEM (STAGES * 36864 + 256)

__global__ void __launch_bounds__(256, 2) gemm_mma(
    const __half* __restrict__ A, int lda,
    const __half* __restrict__ Bt, int ldb, int N,
    float* __restrict__ C, int ldc, int kLen, size_t zStride,
    const float* __restrict__ bias, int mode)
{
    extern __shared__ char smraw[];
    const uint32_t sb = (smem_u32(smraw) + 127u) & ~127u;

    const int tid = threadIdx.x;
    const int lane = tid & 31;
    const int wid = tid >> 5;
    const int wr = wid >> 1;          // 0..3
    const int wc = wid & 1;           // 0..1
    const int bRow = blockIdx.y << 7;
    const int bCol = blockIdx.x << 7;
    const int kBase = blockIdx.z * kLen;

    const __half* Ab = A + (size_t)bRow * lda + kBase;

    const int lrow[4] = { (0 * 256 + tid) >> 3, (1 * 256 + tid) >> 3,
                          (2 * 256 + tid) >> 3, (3 * 256 + tid) >> 3 };
    const int lkq = tid & 7;

    float acc[2][8][4];
#pragma unroll
    for (int mi = 0; mi < 2; mi++)
#pragma unroll
        for (int ni = 0; ni < 8; ni++)
#pragma unroll
            for (int e = 0; e < 4; e++) acc[mi][ni][e] = 0.f;

// async copy one 64-K chunk into stage (cidx % STAGES)
#define S_COPY(cidx)                                                           \
    do {                                                                       \
        const int s_ = (cidx) % STAGES;                                        \
        const int k0_ = (cidx) << 6;                                           \
        const uint32_t sa_ = sb + (uint32_t)s_ * STAGE_T;                      \
        const uint32_t sb_ = sa_ + STAGE_B;                                    \
        _Pragma("unroll")                                                      \
        for (int i = 0; i < 4; i++) {                                          \
            const uint32_t off = ((uint32_t)lrow[i] * STRIDE + lkq * 8) * 2;   \
            const __half* ga =                                                 \
                Ab + (size_t)lrow[i] * lda + k0_ + lkq * 8;                    \
            asm volatile("cp.async.cg.shared.global [%0], [%1], 16;"           \
                         :: "r"(sa_ + off), "l"(ga));                          \
            const int rbr = bCol + lrow[i];                                    \
            const __half* gb =                                                 \
                Bt + (size_t)(rbr < N ? rbr : N - 1) * ldb + kBase + k0_ + lkq * 8; \
            const uint32_t bsz = (rbr < N) ? 16u : 0u;                         \
            asm volatile("cp.async.cg.shared.global [%0], [%1], 16, %2;"       \
                         :: "r"(sb_ + off), "l"(gb), "r"(bsz));                \
        }                                                                      \
    } while (0)

    const int nchunk = kLen >> 6;
    int cread = 0;
#pragma unroll
    for (int i = 0; i < STAGES - 1; i++) {
        if (cread < nchunk) { S_COPY(cread); cread++; }
        asm volatile("cp.async.commit_group;" ::: "memory");
    }

    // ldmatrix lane address components
    const uint32_t aRow = (uint32_t)(wr * 32 + (lane & 7) + ((lane >> 3) & 1) * 8);
    const uint32_t aKof = (uint32_t)((lane >> 4) * 8);
    const uint32_t bRowL = (uint32_t)(wc * 64 + (lane & 7) + ((lane >> 4) << 3));
    const uint32_t bKof = (uint32_t)(((lane >> 3) & 1) * 8);

    for (int c = 0; c < nchunk; c++) {
        asm volatile("cp.async.wait_group %0;" :: "n"(STAGES - 2) : "memory");
        __syncthreads();

        if (cread < nchunk) { S_COPY(cread); cread++; }
        asm volatile("cp.async.commit_group;" ::: "memory");

        const int s = c % STAGES;
        const uint32_t sAs = sb + (uint32_t)s * STAGE_T;
        const uint32_t sBs = sAs + STAGE_B;

#pragma unroll
        for (int ks = 0; ks < 4; ks++) {
            uint32_t afr[2][4];
#pragma unroll
            for (int mi = 0; mi < 2; mi++) {
                uint32_t ad = sAs + ((aRow + mi * 16) * STRIDE + ks * 16 + aKof) * 2;
                ldsm_x4(ad, afr[mi][0], afr[mi][1], afr[mi][2], afr[mi][3]);
            }
            uint32_t bfr[8][2];
#pragma unroll
            for (int nq = 0; nq < 4; nq++) {
                uint32_t bd = sBs + ((bRowL + nq * 16) * STRIDE + ks * 16 + bKof) * 2;
                uint32_t r0, r1, r2, r3;
                ldsm_x4(bd, r0, r1, r2, r3);   // non-trans: Bt rows ARE col-major B
                bfr[nq * 2][0] = r0; bfr[nq * 2][1] = r1;
                bfr[nq * 2 + 1][0] = r2; bfr[nq * 2 + 1][1] = r3;
            }
#pragma unroll
            for (int mi = 0; mi < 2; mi++)
#pragma unroll
                for (int ni = 0; ni < 8; ni++)
                    mma16816(acc[mi][ni], afr[mi], bfr[ni][0], bfr[ni][1]);
        }
    }

    // epilogue
    float* Cz = C + (size_t)blockIdx.z * zStride;
#pragma unroll
    for (int mi = 0; mi < 2; mi++) {
#pragma unroll
        for (int ni = 0; ni < 8; ni++) {
            const int col = bCol + wc * 64 + ni * 8 + (lane & 3) * 2;
            if (col >= N) continue;
            const int r0 = bRow + wr * 32 + mi * 16 + (lane >> 2);
            float v0 = acc[mi][ni][0], v1 = acc[mi][ni][1];
            float v2 = acc[mi][ni][2], v3 = acc[mi][ni][3];
            if (mode == 1) {
                float b0 = bias[col], b1 = bias[col + 1];
                v0 += b0; v1 += b1; v2 += b0; v3 += b1;
                v0 = (v0 > 20.f) ? v0 : log1pf(__expf(v0));
                v1 = (v1 > 20.f) ? v1 : log1pf(__expf(v1));
                v2 = (v2 > 20.f) ? v2 : log1pf(__expf(v2));
                v3 = (v3 > 20.f) ? v3 : log1pf(__expf(v3));
            }
            *(float2*)&Cz[(size_t)r0 * ldc + col] = make_float2(v0, v1);
            *(float2*)&Cz[(size_t)(r0 + 8) * ldc + col] = make_float2(v2, v3);
        }
    }
}

// reduce split-K partials of proj
__global__ void reduce_proj()
{
    int i = blockIdx.x * 256 + threadIdx.x;
    if (i >= ROWS * PROJ_N) return;
    float s = 0.f;
#pragma unroll
    for (int p = 0; p < KSPLIT; p++) s += g_projp[(size_t)p * ROWS * PROJ_N + i];
    g_proj[i] = s;
}

// ---------------- conversion kernels ----------------
// A-side split: in f32 [M][K] (row stride ldin) -> out fp16 [M][2K] = [hi|lo]
__global__ void rsplit(const float* __restrict__ in, int ldin, int M, int K,
                       __half* __restrict__ out)
{
    int i = blockIdx.x * 256 + threadIdx.x;
    if (i >= M * K) return;
    int m = i / K, k = i - m * K;
    float v = in[(size_t)m * ldin + k];
    __half h = __float2half(v);
    __half l = __float2half(v - __half2float(h));
    size_t base = (size_t)m * (2 * K);
    out[base + k] = h;
    out[base + K + k] = l;
}

// B-side transpose + split: in f32 [K][N] -> out fp16 [N][2K] = [hi|hi]
__global__ void tsplit(const float* __restrict__ in, int K, int N,
                       __half* __restrict__ out)
{
    __shared__ float t[32][33];
    int k0 = blockIdx.y * 32, n0 = blockIdx.x * 32;
    int k = k0 + threadIdx.y, n = n0 + threadIdx.x;
    t[threadIdx.y][threadIdx.x] = (k < K && n < N) ? in[(size_t)k * N + n] : 0.f;
    __syncthreads();
    int on = n0 + threadIdx.y, ok = k0 + threadIdx.x;
    if (on < N && ok < K) {
        float v = t[threadIdx.x][threadIdx.y];
        __half h = __float2half(v);
        size_t base = (size_t)on * (2 * K);
        out[base + ok] = h;
        out[base + K + ok] = h;
    }
}

// ---------------- conv + silu: sliding-window, 64 t-steps per thread -------
#define CONV_TT 64
__global__ void __launch_bounds__(256) conv_kernel(
    const float* __restrict__ conv_state,
    const float* __restrict__ conv_w,
    const float* __restrict__ conv_b)
{
    const int d = blockIdx.x * 256 + threadIdx.x;
    const int t0 = blockIdx.y * CONV_TT;
    const int b = blockIdx.z;

    const float w0 = conv_w[d * D_CONV + 0];
    const float w1 = conv_w[d * D_CONV + 1];
    const float w2 = conv_w[d * D_CONV + 2];
    const float w3 = conv_w[d * D_CONV + 3];
    const float cb = conv_b[d];

    const float* xin = g_xz + (size_t)b * T_LEN * (2 * D_INNER) + d;

    float v0, v1, v2;
    if (t0 == 0) {
        v0 = conv_state[((size_t)b * D_INNER + d) * (D_CONV - 1) + 0];
        v1 = conv_state[((size_t)b * D_INNER + d) * (D_CONV - 1) + 1];
        v2 = conv_state[((size_t)b * D_INNER + d) * (D_CONV - 1) + 2];
    } else {
        v0 = xin[(size_t)(t0 - 3) * (2 * D_INNER)];
        v1 = xin[(size_t)(t0 - 2) * (2 * D_INNER)];
        v2 = xin[(size_t)(t0 - 1) * (2 * D_INNER)];
    }

    float* xcv = g_xconv + (size_t)b * T_LEN * D_INNER + d;
    __half* xcs = g_xcs + (size_t)b * T_LEN * (2 * D_INNER) + d;

#pragma unroll 4
    for (int i = 0; i < CONV_TT; i++) {
        const int t = t0 + i;
        const float xn = xin[(size_t)t * (2 * D_INNER)];
        float acc = cb;
        acc = fmaf(w0, v0, acc);
        acc = fmaf(w1, v1, acc);
        acc = fmaf(w2, v2, acc);
        acc = fmaf(w3, xn, acc);
        const float sig = 1.f / (1.f + __expf(-acc));
        const float r = acc * sig;
        xcv[(size_t)t * D_INNER] = r;
        const __half h = __float2half(r);
        const __half l = __float2half(r - __half2float(h));
        const size_t base = (size_t)t * (2 * D_INNER);
        xcs[base] = h;
        xcs[base + D_INNER] = l;
        v0 = v1; v1 = v2; v2 = xn;
    }
}

__global__ void convstate_kernel(float* __restrict__ outp)
{
    int idx = blockIdx.x * 256 + threadIdx.x;
    if (idx >= B_SZ * D_INNER * (D_CONV - 1)) return;
    int j = idx % (D_CONV - 1);
    int d = (idx / (D_CONV - 1)) % D_INNER;
    int b = idx / (D_INNER * (D_CONV - 1));
    outp[idx] = g_xz[((size_t)b * T_LEN + (T_LEN - (D_CONV - 1) + j)) * (2 * D_INNER) + d];
}

// ---------------- selective scan (emits A-side fp16 split y) ----------------
__global__ void __launch_bounds__(256) scan8(const float* __restrict__ ssm0,
                                             const float* __restrict__ A_log,
                                             const float* __restrict__ D_skip,
                                             float* __restrict__ h_out)
{
    int idx = blockIdx.x * 256 + threadIdx.x;
    int s = idx & 7;
    int d = (idx >> 3) & (D_INNER - 1);
    int b = idx >> 14;
    int n0 = 2 * s;

    float2 hv = *(const float2*)&ssm0[((size_t)b * D_INNER + d) * D_STATE + n0];
    float2 al = *(const float2*)&A_log[d * D_STATE + n0];
    float A0 = -__expf(al.x), A1 = -__expf(al.y);
    float dsk = D_skip[d];

    const float* dt_p = g_dt    + (size_t)b * T_LEN * D_INNER + d;
    const float* xc_p = g_xconv + (size_t)b * T_LEN * D_INNER + d;
    const float* z_p  = g_xz    + (size_t)b * T_LEN * (2 * D_INNER) + D_INNER + d;
    const float* bc_p = g_proj  + (size_t)b * T_LEN * PROJ_N + DT_RANK + n0;
    __half* ys = g_ys + (size_t)b * T_LEN * (2 * D_INNER) + d;

    float dt_b[2], xc_b[2], z_b[2];
    float2 B_b[2], C_b[2];
#pragma unroll
    for (int p = 0; p < 2; p++) {
        dt_b[p] = dt_p[(size_t)p * D_INNER];
        xc_b[p] = xc_p[(size_t)p * D_INNER];
        z_b[p]  = z_p[(size_t)p * 2 * D_INNER];
        B_b[p]  = *(const float2*)(bc_p + (size_t)p * PROJ_N);
        C_b[p]  = *(const float2*)(bc_p + (size_t)p * PROJ_N + D_STATE);
    }

    for (int t = 0; t < T_LEN; t++) {
        const int cur = t & 1;
        float dt = dt_b[cur], xc = xc_b[cur], z = z_b[cur];
        float2 Bv = B_b[cur], Cv = C_b[cur];
        if (t + 2 < T_LEN) {
            size_t o = (size_t)(t + 2);
            dt_b[cur] = dt_p[o * D_INNER];
            xc_b[cur] = xc_p[o * D_INNER];
            z_b[cur]  = z_p[o * 2 * D_INNER];
            B_b[cur]  = *(const float2*)(bc_p + o * PROJ_N);
            C_b[cur]  = *(const float2*)(bc_p + o * PROJ_N + D_STATE);
        }
        float e0 = __expf(dt * A0);
        float e1 = __expf(dt * A1);
        float dx = dt * xc;
        hv.x = fmaf(e0, hv.x, dx * Bv.x);
        hv.y = fmaf(e1, hv.y, dx * Bv.y);
        float r = fmaf(hv.x, Cv.x, hv.y * Cv.y);
        r += __shfl_xor_sync(0xffffffffu, r, 1, 8);
        r += __shfl_xor_sync(0xffffffffu, r, 2, 8);
        r += __shfl_xor_sync(0xffffffffu, r, 4, 8);
        if (s == 0) {
            float yv = fmaf(dsk, xc, r);
            float sz = z / (1.f + __expf(-z));
            yv *= sz;
            __half h = __float2half(yv);
            __half l = __float2half(yv - __half2float(h));
            size_t base = (size_t)t * (2 * D_INNER);
            ys[base] = h;
            ys[base + D_INNER] = l;
        }
    }
    *(float2*)&h_out[((size_t)b * D_INNER + d) * D_STATE + n0] = hv;
}

// ----------------------------------------------------------------------------
extern "C" void kernel_launch(void* const* d_in, const int* in_sizes, int n_in,
                              void* d_out, int out_size)
{
    const float* x          = (const float*)d_in[0];
    const float* ssm_state  = (const float*)d_in[1];
    const float* conv_state = (const float*)d_in[2];
    const float* w_in       = (const float*)d_in[3];
    const float* conv_w     = (const float*)d_in[4];
    const float* conv_b     = (const float*)d_in[5];
    const float* w_x        = (const float*)d_in[6];
    const float* w_dt       = (const float*)d_in[7];
    const float* b_dt       = (const float*)d_in[8];
    const float* A_log      = (const float*)d_in[9];
    const float* D_skip     = (const float*)d_in[10];
    const float* w_out      = (const float*)d_in[11];
    float* out = (float*)d_out;

    cudaStreamCaptureStatus cs = cudaStreamCaptureStatusNone;
    cudaStreamIsCapturing(cudaStreamLegacy, &cs);
    if (cs == cudaStreamCaptureStatusNone)
        cudaFuncSetAttribute(gemm_mma, cudaFuncAttributeMaxDynamicSharedMemorySize, GEMM_SMEM);

    float *xz, *proj, *projp, *dt;
    __half *xs, *wint, *xcs, *wxt, *dtin, *wdtt, *ys, *wott;
    cudaGetSymbolAddress((void**)&xz,    g_xz);
    cudaGetSymbolAddress((void**)&proj,  g_proj);
    cudaGetSymbolAddress((void**)&projp, g_projp);
    cudaGetSymbolAddress((void**)&dt,    g_dt);
    cudaGetSymbolAddress((void**)&xs,    g_xs);
    cudaGetSymbolAddress((void**)&wint,  g_wint);
    cudaGetSymbolAddress((void**)&xcs,   g_xcs);
    cudaGetSymbolAddress((void**)&wxt,   g_wxt);
    cudaGetSymbolAddress((void**)&dtin,  g_dtin);
    cudaGetSymbolAddress((void**)&wdtt,  g_wdtt);
    cudaGetSymbolAddress((void**)&ys,    g_ys);
    cudaGetSymbolAddress((void**)&wott,  g_wott);

    // Launch order keeps gemm1 as the 4th launch (ncu capture slot).
    rsplit<<<(ROWS * DIM + 255) / 256, 256>>>(x, DIM, ROWS, DIM, xs);          // 1
    tsplit<<<dim3((2 * D_INNER) / 32, DIM / 32), dim3(32, 32)>>>(w_in, DIM, 2 * D_INNER, wint); // 2
    tsplit<<<dim3(DIM / 32, D_INNER / 32), dim3(32, 32)>>>(w_out, D_INNER, DIM, wott);          // 3

    // 4) xz = x @ w_in   (Kp = 2048)  <-- profiled launch
    gemm_mma<<<dim3(32, 32, 1), 256, GEMM_SMEM>>>(
        xs, 2 * DIM, wint, 2 * DIM, 2 * D_INNER,
        xz, 2 * D_INNER, 2 * DIM, 0, nullptr, 0);

    // 5) depthwise conv + silu
    conv_kernel<<<dim3(D_INNER / 256, T_LEN / CONV_TT, B_SZ), 256>>>(conv_state, conv_w, conv_b);
    // 6) new conv state
    convstate_kernel<<<(B_SZ * D_INNER * (D_CONV - 1) + 255) / 256, 256>>>(out + OFF_CONV);
    // 7)
    tsplit<<<dim3(3, D_INNER / 32), dim3(32, 32)>>>(w_x, D_INNER, PROJ_N, wxt);

    // 8) proj = x_conv @ w_x  (Kp = 4096, split-K=4 -> 1024 per z)
    gemm_mma<<<dim3(1, 32, KSPLIT), 256, GEMM_SMEM>>>(
        xcs, 2 * D_INNER, wxt, 2 * D_INNER, PROJ_N,
        projp, PROJ_N, (2 * D_INNER) / KSPLIT, (size_t)ROWS * PROJ_N, nullptr, 0);
    // 9)
    reduce_proj<<<(ROWS * PROJ_N + 255) / 256, 256>>>();

    // 10-11) dt inputs
    rsplit<<<(ROWS * DT_RANK + 255) / 256, 256>>>(proj, PROJ_N, ROWS, DT_RANK, dtin);
    tsplit<<<dim3(D_INNER / 32, 2), dim3(32, 32)>>>(w_dt, DT_RANK, D_INNER, wdtt);

    // 12) dt = softplus(proj[:, :64] @ w_dt + b_dt)  (Kp = 128)
    gemm_mma<<<dim3(16, 32, 1), 256, GEMM_SMEM>>>(
        dtin, 2 * DT_RANK, wdtt, 2 * DT_RANK, D_INNER,
        dt, D_INNER, 2 * DT_RANK, 0, b_dt, 1);

    // 13) selective scan
    scan8<<<(B_SZ * D_INNER * 8) / 256, 256>>>(ssm_state, A_log, D_skip, out + OFF_H);

    // 14) out = y_gated @ w_out  (Kp = 4096)
    gemm_mma<<<dim3(8, 32, 1), 256, GEMM_SMEM>>>(
        ys, 2 * D_INNER, wott, 2 * D_INNER, DIM,
        out, DIM, 2 * D_INNER, 0, nullptr, 0);
}

// round 11
// speedup vs baseline: 3.1796x; 1.0325x over previous
#include <cuda_runtime.h>
#include <cuda_fp16.h>
#include <math.h>
#include <stdint.h>

// Problem constants
#define DIM      1024
#define D_INNER  2048
#define D_STATE  16
#define D_CONV   4
#define DT_RANK  64
#define B_SZ     2
#define T_LEN    2048
#define ROWS     (B_SZ * T_LEN)           // 4096
#define PROJ_N   (DT_RANK + 2 * D_STATE)  // 96
#define KSPLIT   4

// Output offsets (floats): out | h_final | new_conv_state
#define OFF_H    (ROWS * DIM)
#define OFF_CONV (OFF_H + B_SZ * D_INNER * D_STATE)

// ---------------- scratch (device globals) ----------------
__device__ float g_xz[(size_t)ROWS * (2 * D_INNER)];   // x_in | z
__device__ float g_xconv[(size_t)ROWS * D_INNER];
__device__ float g_projp[(size_t)KSPLIT * ROWS * PROJ_N];
__device__ float g_proj[(size_t)ROWS * PROJ_N];
__device__ float g_dt[(size_t)ROWS * D_INNER];
// fp16 split operands. A side: [hi | lo] (K doubled). B side: hi only —
// the GEMM wraps its B k-index with a mask, so chunks >= K reread hi.
__device__ __align__(16) __half g_xs  [(size_t)ROWS * (2 * DIM)];
__device__ __align__(16) __half g_wint[(size_t)(2 * D_INNER) * DIM];
__device__ __align__(16) __half g_xcs [(size_t)ROWS * (2 * D_INNER)];
__device__ __align__(16) __half g_wxt [(size_t)PROJ_N * D_INNER];
__device__ __align__(16) __half g_dtin[(size_t)ROWS * (2 * DT_RANK)];
__device__ __align__(16) __half g_wdtt[(size_t)D_INNER * DT_RANK];
__device__ __align__(16) __half g_ys  [(size_t)ROWS * (2 * D_INNER)];
__device__ __align__(16) __half g_wott[(size_t)DIM * D_INNER];

// ---------------- mma helpers ----------------
__device__ __forceinline__ uint32_t smem_u32(const void* p) {
    uint32_t a;
    asm("{ .reg .u64 t; cvta.to.shared.u64 t, %1; cvt.u32.u64 %0, t; }" : "=r"(a) : "l"(p));
    return a;
}
__device__ __forceinline__ void ldsm_x4(uint32_t addr, uint32_t& r0, uint32_t& r1,
                                        uint32_t& r2, uint32_t& r3) {
    asm volatile("ldmatrix.sync.aligned.m8n8.x4.shared.b16 {%0,%1,%2,%3}, [%4];"
                 : "=r"(r0), "=r"(r1), "=r"(r2), "=r"(r3) : "r"(addr));
}
__device__ __forceinline__ void mma16816(float* d, const uint32_t* a,
                                         uint32_t b0, uint32_t b1) {
    asm volatile("mma.sync.aligned.m16n8k16.row.col.f32.f16.f16.f32 "
                 "{%0,%1,%2,%3}, {%4,%5,%6,%7}, {%8,%9}, {%0,%1,%2,%3};"
                 : "+f"(d[0]), "+f"(d[1]), "+f"(d[2]), "+f"(d[3])
                 : "r"(a[0]), "r"(a[1]), "r"(a[2]), "r"(a[3]), "r"(b0), "r"(b1));
}

// ----------------------------------------------------------------------------
// fp16 HMMA GEMM, cp.async 3-stage, 2 CTAs/SM.
// C[M,N] = A[M,Kp] * B'[N,Kp]^T where B'[n][k] = Bt[n][k & kbMask] (hi reuse).
// 128x128 CTA tile, BK=64, 8 warps (4x2), warp tile 32x64 via m16n8k16.
// Split-K via gridDim.z. mode 1: +bias[col] then fast softplus.
// ----------------------------------------------------------------------------
#define STRIDE  72
#define STAGE_B 18432u
#define STAGE_T 36864u
#define STAGES  3
#define GEMM_SMEM (STAGES * 36864 + 256)

__global__ void __launch_bounds__(256, 2) gemm_mma(
    const __half* __restrict__ A, int lda,
    const __half* __restrict__ Bt, int ldb, int kbMask, int N,
    float* __restrict__ C, int ldc, int kLen, size_t zStride,
    const float* __restrict__ bias, int mode)
{
    extern __shared__ char smraw[];
    const uint32_t sb = (smem_u32(smraw) + 127u) & ~127u;

    const int tid = threadIdx.x;
    const int lane = tid & 31;
    const int wid = tid >> 5;
    const int wr = wid >> 1;
    const int wc = wid & 1;
    const int bRow = blockIdx.y << 7;
    const int bCol = blockIdx.x << 7;
    const int kBase = blockIdx.z * kLen;

    const __half* Ab = A + (size_t)bRow * lda + kBase;

    const int lrow[4] = { (0 * 256 + tid) >> 3, (1 * 256 + tid) >> 3,
                          (2 * 256 + tid) >> 3, (3 * 256 + tid) >> 3 };
    const int lkq = tid & 7;

    float acc[2][8][4];
#pragma unroll
    for (int mi = 0; mi < 2; mi++)
#pragma unroll
        for (int ni = 0; ni < 8; ni++)
#pragma unroll
            for (int e = 0; e < 4; e++) acc[mi][ni][e] = 0.f;

#define S_COPY(cidx)                                                           \
    do {                                                                       \
        const int s_ = (cidx) % STAGES;                                        \
        const int k0_ = (cidx) << 6;                                           \
        const int kb_ = (kBase + k0_) & kbMask;                                \
        const uint32_t sa_ = sb + (uint32_t)s_ * STAGE_T;                      \
        const uint32_t sb_ = sa_ + STAGE_B;                                    \
        _Pragma("unroll")                                                      \
        for (int i = 0; i < 4; i++) {                                          \
            const uint32_t off = ((uint32_t)lrow[i] * STRIDE + lkq * 8) * 2;   \
            const __half* ga =                                                 \
                Ab + (size_t)lrow[i] * lda + k0_ + lkq * 8;                    \
            asm volatile("cp.async.cg.shared.global [%0], [%1], 16;"           \
                         :: "r"(sa_ + off), "l"(ga));                          \
            const int rbr = bCol + lrow[i];                                    \
            const __half* gb =                                                 \
                Bt + (size_t)(rbr < N ? rbr : N - 1) * ldb + kb_ + lkq * 8;    \
            const uint32_t bsz = (rbr < N) ? 16u : 0u;                         \
            asm volatile("cp.async.cg.shared.global [%0], [%1], 16, %2;"       \
                         :: "r"(sb_ + off), "l"(gb), "r"(bsz));                \
        }                                                                      \
    } while (0)

    const int nchunk = kLen >> 6;
    int cread = 0;
#pragma unroll
    for (int i = 0; i < STAGES - 1; i++) {
        if (cread < nchunk) { S_COPY(cread); cread++; }
        asm volatile("cp.async.commit_group;" ::: "memory");
    }

    const uint32_t aRow = (uint32_t)(wr * 32 + (lane & 7) + ((lane >> 3) & 1) * 8);
    const uint32_t aKof = (uint32_t)((lane >> 4) * 8);
    const uint32_t bRowL = (uint32_t)(wc * 64 + (lane & 7) + ((lane >> 4) << 3));
    const uint32_t bKof = (uint32_t)(((lane >> 3) & 1) * 8);

    for (int c = 0; c < nchunk; c++) {
        asm volatile("cp.async.wait_group %0;" :: "n"(STAGES - 2) : "memory");
        __syncthreads();

        if (cread < nchunk) { S_COPY(cread); cread++; }
        asm volatile("cp.async.commit_group;" ::: "memory");

        const int s = c % STAGES;
        const uint32_t sAs = sb + (uint32_t)s * STAGE_T;
        const uint32_t sBs = sAs + STAGE_B;

#pragma unroll
        for (int ks = 0; ks < 4; ks++) {
            uint32_t afr[2][4];
#pragma unroll
            for (int mi = 0; mi < 2; mi++) {
                uint32_t ad = sAs + ((aRow + mi * 16) * STRIDE + ks * 16 + aKof) * 2;
                ldsm_x4(ad, afr[mi][0], afr[mi][1], afr[mi][2], afr[mi][3]);
            }
            uint32_t bfr[8][2];
#pragma unroll
            for (int nq = 0; nq < 4; nq++) {
                uint32_t bd = sBs + ((bRowL + nq * 16) * STRIDE + ks * 16 + bKof) * 2;
                uint32_t r0, r1, r2, r3;
                ldsm_x4(bd, r0, r1, r2, r3);
                bfr[nq * 2][0] = r0; bfr[nq * 2][1] = r1;
                bfr[nq * 2 + 1][0] = r2; bfr[nq * 2 + 1][1] = r3;
            }
#pragma unroll
            for (int mi = 0; mi < 2; mi++)
#pragma unroll
                for (int ni = 0; ni < 8; ni++)
                    mma16816(acc[mi][ni], afr[mi], bfr[ni][0], bfr[ni][1]);
        }
    }

    // epilogue (mode 1: fast softplus)
    float* Cz = C + (size_t)blockIdx.z * zStride;
#pragma unroll
    for (int mi = 0; mi < 2; mi++) {
#pragma unroll
        for (int ni = 0; ni < 8; ni++) {
            const int col = bCol + wc * 64 + ni * 8 + (lane & 3) * 2;
            if (col >= N) continue;
            const int r0 = bRow + wr * 32 + mi * 16 + (lane >> 2);
            float v0 = acc[mi][ni][0], v1 = acc[mi][ni][1];
            float v2 = acc[mi][ni][2], v3 = acc[mi][ni][3];
            if (mode == 1) {
                float b0 = bias[col], b1 = bias[col + 1];
                v0 += b0; v1 += b1; v2 += b0; v3 += b1;
                v0 = (v0 > 15.f) ? v0 : __logf(1.f + __expf(v0));
                v1 = (v1 > 15.f) ? v1 : __logf(1.f + __expf(v1));
                v2 = (v2 > 15.f) ? v2 : __logf(1.f + __expf(v2));
                v3 = (v3 > 15.f) ? v3 : __logf(1.f + __expf(v3));
            }
            *(float2*)&Cz[(size_t)r0 * ldc + col] = make_float2(v0, v1);
            *(float2*)&Cz[(size_t)(r0 + 8) * ldc + col] = make_float2(v2, v3);
        }
    }
}

// reduce split-K partials of proj; also emit dtin fp16 split for cols < 64
__global__ void reduce_proj(__half* __restrict__ dtin)
{
    int i = blockIdx.x * 256 + threadIdx.x;
    if (i >= ROWS * PROJ_N) return;
    float s = 0.f;
#pragma unroll
    for (int p = 0; p < KSPLIT; p++) s += g_projp[(size_t)p * ROWS * PROJ_N + i];
    g_proj[i] = s;
    int m = i / PROJ_N, col = i - m * PROJ_N;
    if (col < DT_RANK) {
        __half h = __float2half(s);
        __half l = __float2half(s - __half2float(h));
        size_t base = (size_t)m * (2 * DT_RANK);
        dtin[base + col] = h;
        dtin[base + DT_RANK + col] = l;
    }
}

// ---------------- conversion kernels ----------------
// A-side split: f32 [M][K] -> fp16 [M][2K] = [hi|lo]
__global__ void rsplit(const float* __restrict__ in, int ldin, int M, int K,
                       __half* __restrict__ out)
{
    int i = blockIdx.x * 256 + threadIdx.x;
    if (i >= M * K) return;
    int m = i / K, k = i - m * K;
    float v = in[(size_t)m * ldin + k];
    __half h = __float2half(v);
    __half l = __float2half(v - __half2float(h));
    size_t base = (size_t)m * (2 * K);
    out[base + k] = h;
    out[base + K + k] = l;
}

// B-side transpose: f32 [K][N] -> fp16 [N][K] hi only
__global__ void tsplit(const float* __restrict__ in, int K, int N,
                       __half* __restrict__ out)
{
    __shared__ float t[32][33];
    int k0 = blockIdx.y * 32, n0 = blockIdx.x * 32;
    int k = k0 + threadIdx.y, n = n0 + threadIdx.x;
    t[threadIdx.y][threadIdx.x] = (k < K && n < N) ? in[(size_t)k * N + n] : 0.f;
    __syncthreads();
    int on = n0 + threadIdx.y, ok = k0 + threadIdx.x;
    if (on < N && ok < K)
        out[(size_t)on * K + ok] = __float2half(t[threadIdx.x][threadIdx.y]);
}

// ---------------- conv + silu: sliding-window, 64 t-steps per thread -------
#define CONV_TT 64
__global__ void __launch_bounds__(256) conv_kernel(
    const float* __restrict__ conv_state,
    const float* __restrict__ conv_w,
    const float* __restrict__ conv_b)
{
    const int d = blockIdx.x * 256 + threadIdx.x;
    const int t0 = blockIdx.y * CONV_TT;
    const int b = blockIdx.z;

    const float w0 = conv_w[d * D_CONV + 0];
    const float w1 = conv_w[d * D_CONV + 1];
    const float w2 = conv_w[d * D_CONV + 2];
    const float w3 = conv_w[d * D_CONV + 3];
    const float cb = conv_b[d];

    const float* xin = g_xz + (size_t)b * T_LEN * (2 * D_INNER) + d;

    float v0, v1, v2;
    if (t0 == 0) {
        v0 = conv_state[((size_t)b * D_INNER + d) * (D_CONV - 1) + 0];
        v1 = conv_state[((size_t)b * D_INNER + d) * (D_CONV - 1) + 1];
        v2 = conv_state[((size_t)b * D_INNER + d) * (D_CONV - 1) + 2];
    } else {
        v0 = xin[(size_t)(t0 - 3) * (2 * D_INNER)];
        v1 = xin[(size_t)(t0 - 2) * (2 * D_INNER)];
        v2 = xin[(size_t)(t0 - 1) * (2 * D_INNER)];
    }

    float* xcv = g_xconv + (size_t)b * T_LEN * D_INNER + d;
    __half* xcs = g_xcs + (size_t)b * T_LEN * (2 * D_INNER) + d;

#pragma unroll 4
    for (int i = 0; i < CONV_TT; i++) {
        const int t = t0 + i;
        const float xn = xin[(size_t)t * (2 * D_INNER)];
        float acc = cb;
        acc = fmaf(w0, v0, acc);
        acc = fmaf(w1, v1, acc);
        acc = fmaf(w2, v2, acc);
        acc = fmaf(w3, xn, acc);
        const float sig = 1.f / (1.f + __expf(-acc));
        const float r = acc * sig;
        xcv[(size_t)t * D_INNER] = r;
        const __half h = __float2half(r);
        const __half l = __float2half(r - __half2float(h));
        const size_t base = (size_t)t * (2 * D_INNER);
        xcs[base] = h;
        xcs[base + D_INNER] = l;
        v0 = v1; v1 = v2; v2 = xn;
    }
}

__global__ void convstate_kernel(float* __restrict__ outp)
{
    int idx = blockIdx.x * 256 + threadIdx.x;
    if (idx >= B_SZ * D_INNER * (D_CONV - 1)) return;
    int j = idx % (D_CONV - 1);
    int d = (idx / (D_CONV - 1)) % D_INNER;
    int b = idx / (D_INNER * (D_CONV - 1));
    outp[idx] = g_xz[((size_t)b * T_LEN + (T_LEN - (D_CONV - 1) + j)) * (2 * D_INNER) + d];
}

// ---------------- selective scan: 4 threads per (b,d), 4 states each -------
__global__ void __launch_bounds__(128) scan4(const float* __restrict__ ssm0,
                                             const float* __restrict__ A_log,
                                             const float* __restrict__ D_skip,
                                             float* __restrict__ h_out)
{
    int idx = blockIdx.x * 128 + threadIdx.x;   // 0..16383
    int s = idx & 3;
    int d = (idx >> 2) & (D_INNER - 1);
    int b = idx >> 13;
    int n0 = 4 * s;

    float4 hv = *(const float4*)&ssm0[((size_t)b * D_INNER + d) * D_STATE + n0];
    float4 al = *(const float4*)&A_log[d * D_STATE + n0];
    float A0 = -__expf(al.x), A1 = -__expf(al.y);
    float A2 = -__expf(al.z), A3 = -__expf(al.w);
    float dsk = D_skip[d];

    const float* dt_p = g_dt    + (size_t)b * T_LEN * D_INNER + d;
    const float* xc_p = g_xconv + (size_t)b * T_LEN * D_INNER + d;
    const float* z_p  = g_xz    + (size_t)b * T_LEN * (2 * D_INNER) + D_INNER + d;
    const float* bc_p = g_proj  + (size_t)b * T_LEN * PROJ_N + DT_RANK + n0;
    __half* ys = g_ys + (size_t)b * T_LEN * (2 * D_INNER) + d;

    float dt_b[2], xc_b[2], z_b[2];
    float4 B_b[2], C_b[2];
#pragma unroll
    for (int p = 0; p < 2; p++) {
        dt_b[p] = dt_p[(size_t)p * D_INNER];
        xc_b[p] = xc_p[(size_t)p * D_INNER];
        z_b[p]  = z_p[(size_t)p * 2 * D_INNER];
        B_b[p]  = *(const float4*)(bc_p + (size_t)p * PROJ_N);
        C_b[p]  = *(const float4*)(bc_p + (size_t)p * PROJ_N + D_STATE);
    }

    for (int t = 0; t < T_LEN; t++) {
        const int cur = t & 1;
        float dt = dt_b[cur], xc = xc_b[cur], z = z_b[cur];
        float4 Bv = B_b[cur], Cv = C_b[cur];
        if (t + 2 < T_LEN) {
            size_t o = (size_t)(t + 2);
            dt_b[cur] = dt_p[o * D_INNER];
            xc_b[cur] = xc_p[o * D_INNER];
            z_b[cur]  = z_p[o * 2 * D_INNER];
            B_b[cur]  = *(const float4*)(bc_p + o * PROJ_N);
            C_b[cur]  = *(const float4*)(bc_p + o * PROJ_N + D_STATE);
        }
        float e0 = __expf(dt * A0);
        float e1 = __expf(dt * A1);
        float e2 = __expf(dt * A2);
        float e3 = __expf(dt * A3);
        float dx = dt * xc;
        hv.x = fmaf(e0, hv.x, dx * Bv.x);
        hv.y = fmaf(e1, hv.y, dx * Bv.y);
        hv.z = fmaf(e2, hv.z, dx * Bv.z);
        hv.w = fmaf(e3, hv.w, dx * Bv.w);
        float r = hv.x * Cv.x;
        r = fmaf(hv.y, Cv.y, r);
        r = fmaf(hv.z, Cv.z, r);
        r = fmaf(hv.w, Cv.w, r);
        r += __shfl_xor_sync(0xffffffffu, r, 1, 4);
        r += __shfl_xor_sync(0xffffffffu, r, 2, 4);
        if (s == 0) {
            float yv = fmaf(dsk, xc, r);
            float sz = z / (1.f + __expf(-z));
            yv *= sz;
            __half h = __float2half(yv);
            __half l = __float2half(yv - __half2float(h));
            size_t base = (size_t)t * (2 * D_INNER);
            ys[base] = h;
            ys[base + D_INNER] = l;
        }
    }
    *(float4*)&h_out[((size_t)b * D_INNER + d) * D_STATE + n0] = hv;
}

// ----------------------------------------------------------------------------
extern "C" void kernel_launch(void* const* d_in, const int* in_sizes, int n_in,
                              void* d_out, int out_size)
{
    const float* x          = (const float*)d_in[0];
    const float* ssm_state  = (const float*)d_in[1];
    const float* conv_state = (const float*)d_in[2];
    const float* w_in       = (const float*)d_in[3];
    const float* conv_w     = (const float*)d_in[4];
    const float* conv_b     = (const float*)d_in[5];
    const float* w_x        = (const float*)d_in[6];
    const float* w_dt       = (const float*)d_in[7];
    const float* b_dt       = (const float*)d_in[8];
    const float* A_log      = (const float*)d_in[9];
    const float* D_skip     = (const float*)d_in[10];
    const float* w_out      = (const float*)d_in[11];
    float* out = (float*)d_out;

    cudaStreamCaptureStatus cs = cudaStreamCaptureStatusNone;
    cudaStreamIsCapturing(cudaStreamLegacy, &cs);
    if (cs == cudaStreamCaptureStatusNone)
        cudaFuncSetAttribute(gemm_mma, cudaFuncAttributeMaxDynamicSharedMemorySize, GEMM_SMEM);

    float *xz, *proj, *projp, *dt;
    __half *xs, *wint, *xcs, *wxt, *dtin, *wdtt, *ys, *wott;
    cudaGetSymbolAddress((void**)&xz,    g_xz);
    cudaGetSymbolAddress((void**)&proj,  g_proj);
    cudaGetSymbolAddress((void**)&projp, g_projp);
    cudaGetSymbolAddress((void**)&dt,    g_dt);
    cudaGetSymbolAddress((void**)&xs,    g_xs);
    cudaGetSymbolAddress((void**)&wint,  g_wint);
    cudaGetSymbolAddress((void**)&xcs,   g_xcs);
    cudaGetSymbolAddress((void**)&wxt,   g_wxt);
    cudaGetSymbolAddress((void**)&dtin,  g_dtin);
    cudaGetSymbolAddress((void**)&wdtt,  g_wdtt);
    cudaGetSymbolAddress((void**)&ys,    g_ys);
    cudaGetSymbolAddress((void**)&wott,  g_wott);

    // Launch order keeps gemm1 as the 4th launch (ncu capture slot).
    rsplit<<<(ROWS * DIM + 255) / 256, 256>>>(x, DIM, ROWS, DIM, xs);                   // 1
    tsplit<<<dim3((2 * D_INNER) / 32, DIM / 32), dim3(32, 32)>>>(w_in, DIM, 2 * D_INNER, wint); // 2
    tsplit<<<dim3(DIM / 32, D_INNER / 32), dim3(32, 32)>>>(w_out, D_INNER, DIM, wott);          // 3

    // 4) xz = x @ w_in   (Kp = 2048, B period 1024)  <-- profiled launch
    gemm_mma<<<dim3(32, 32, 1), 256, GEMM_SMEM>>>(
        xs, 2 * DIM, wint, DIM, DIM - 1, 2 * D_INNER,
        xz, 2 * D_INNER, 2 * DIM, 0, nullptr, 0);

    // 5) depthwise conv + silu
    conv_kernel<<<dim3(D_INNER / 256, T_LEN / CONV_TT, B_SZ), 256>>>(conv_state, conv_w, conv_b);
    // 6) new conv state
    convstate_kernel<<<(B_SZ * D_INNER * (D_CONV - 1) + 255) / 256, 256>>>(out + OFF_CONV);
    // 7)
    tsplit<<<dim3(3, D_INNER / 32), dim3(32, 32)>>>(w_x, D_INNER, PROJ_N, wxt);

    // 8) proj = x_conv @ w_x  (Kp = 4096, B period 2048, split-K=4)
    gemm_mma<<<dim3(1, 32, KSPLIT), 256, GEMM_SMEM>>>(
        xcs, 2 * D_INNER, wxt, D_INNER, D_INNER - 1, PROJ_N,
        projp, PROJ_N, (2 * D_INNER) / KSPLIT, (size_t)ROWS * PROJ_N, nullptr, 0);
    // 9) reduce + emit dtin
    reduce_proj<<<(ROWS * PROJ_N + 255) / 256, 256>>>(dtin);
    // 10)
    tsplit<<<dim3(D_INNER / 32, 2), dim3(32, 32)>>>(w_dt, DT_RANK, D_INNER, wdtt);

    // 11) dt = softplus(proj[:, :64] @ w_dt + b_dt)  (Kp = 128, B period 64)
    gemm_mma<<<dim3(16, 32, 1), 256, GEMM_SMEM>>>(
        dtin, 2 * DT_RANK, wdtt, DT_RANK, DT_RANK - 1, D_INNER,
        dt, D_INNER, 2 * DT_RANK, 0, b_dt, 1);

    // 12) selective scan
    scan4<<<(B_SZ * D_INNER * 4) / 128, 128>>>(ssm_state, A_log, D_skip, out + OFF_H);

    // 13) out = y_gated @ w_out  (Kp = 4096, B period 2048)
    gemm_mma<<<dim3(8, 32, 1), 256, GEMM_SMEM>>>(
        ys, 2 * D_INNER, wott, D_INNER, D_INNER - 1, DIM,
        out, DIM, 2 * D_INNER, 0, nullptr, 0);
}

// round 12
// speedup vs baseline: 3.8847x; 1.2218x over previous
#include <cuda_runtime.h>
#include <cuda_fp16.h>
#include <math.h>
#include <stdint.h>

// Problem constants
#define DIM      1024
#define D_INNER  2048
#define D_STATE  16
#define D_CONV   4
#define DT_RANK  64
#define B_SZ     2
#define T_LEN    2048
#define ROWS     (B_SZ * T_LEN)           // 4096
#define PROJ_N   (DT_RANK + 2 * D_STATE)  // 96
#define KSPLIT   4

// Output offsets (floats): out | h_final | new_conv_state
#define OFF_H    (ROWS * DIM)
#define OFF_CONV (OFF_H + B_SZ * D_INNER * D_STATE)

// ---------------- scratch (device globals) ----------------
__device__ float g_xz[(size_t)ROWS * (2 * D_INNER)];   // x_in | z
__device__ float g_xconv[(size_t)ROWS * D_INNER];
__device__ float g_projp[(size_t)KSPLIT * ROWS * PROJ_N];
__device__ float g_proj[(size_t)ROWS * PROJ_N];
__device__ float g_dt[(size_t)ROWS * D_INNER];
// fp16 split operands. A side: [hi | lo] (K doubled). B side: hi only —
// the GEMM wraps its B k-index with a mask, so chunks >= K reread hi.
__device__ __align__(16) __half g_xs  [(size_t)ROWS * (2 * DIM)];
__device__ __align__(16) __half g_wint[(size_t)(2 * D_INNER) * DIM];
__device__ __align__(16) __half g_xcs [(size_t)ROWS * (2 * D_INNER)];
__device__ __align__(16) __half g_wxt [(size_t)PROJ_N * D_INNER];
__device__ __align__(16) __half g_dtin[(size_t)ROWS * (2 * DT_RANK)];
__device__ __align__(16) __half g_wdtt[(size_t)D_INNER * DT_RANK];
__device__ __align__(16) __half g_ys  [(size_t)ROWS * (2 * D_INNER)];
__device__ __align__(16) __half g_wott[(size_t)DIM * D_INNER];

// ---------------- mma helpers ----------------
__device__ __forceinline__ uint32_t smem_u32(const void* p) {
    uint32_t a;
    asm("{ .reg .u64 t; cvta.to.shared.u64 t, %1; cvt.u32.u64 %0, t; }" : "=r"(a) : "l"(p));
    return a;
}
__device__ __forceinline__ void ldsm_x4(uint32_t addr, uint32_t& r0, uint32_t& r1,
                                        uint32_t& r2, uint32_t& r3) {
    asm volatile("ldmatrix.sync.aligned.m8n8.x4.shared.b16 {%0,%1,%2,%3}, [%4];"
                 : "=r"(r0), "=r"(r1), "=r"(r2), "=r"(r3) : "r"(addr));
}
__device__ __forceinline__ void mma16816(float* d, const uint32_t* a,
                                         uint32_t b0, uint32_t b1) {
    asm volatile("mma.sync.aligned.m16n8k16.row.col.f32.f16.f16.f32 "
                 "{%0,%1,%2,%3}, {%4,%5,%6,%7}, {%8,%9}, {%0,%1,%2,%3};"
                 : "+f"(d[0]), "+f"(d[1]), "+f"(d[2]), "+f"(d[3])
                 : "r"(a[0]), "r"(a[1]), "r"(a[2]), "r"(a[3]), "r"(b0), "r"(b1));
}

// ----------------------------------------------------------------------------
// fp16 HMMA GEMM, cp.async 3-stage, 2 CTAs/SM.
// C[M,N] = A[M,Kp] * B'[N,Kp]^T where B'[n][k] = Bt[n][k & kbMask] (hi reuse).
// 128x128 CTA tile, BK=64, 8 warps (4x2), warp tile 32x64 via m16n8k16.
// Split-K via gridDim.z. mode 1: +bias[col] then fast softplus.
// ----------------------------------------------------------------------------
#define STRIDE  72
#define STAGE_B 18432u
#define STAGE_T 36864u
#define STAGES  3
#define GEMM_SMEM (STAGES * 36864 + 256)

__global__ void __launch_bounds__(256, 2) gemm_mma(
    const __half* __restrict__ A, int lda,
    const __half* __restrict__ Bt, int ldb, int kbMask, int N,
    float* __restrict__ C, int ldc, int kLen, size_t zStride,
    const float* __restrict__ bias, int mode)
{
    extern __shared__ char smraw[];
    const uint32_t sb = (smem_u32(smraw) + 127u) & ~127u;

    const int tid = threadIdx.x;
    const int lane = tid & 31;
    const int wid = tid >> 5;
    const int wr = wid >> 1;
    const int wc = wid & 1;
    const int bRow = blockIdx.y << 7;
    const int bCol = blockIdx.x << 7;
    const int kBase = blockIdx.z * kLen;

    const __half* Ab = A + (size_t)bRow * lda + kBase;

    const int lrow[4] = { (0 * 256 + tid) >> 3, (1 * 256 + tid) >> 3,
                          (2 * 256 + tid) >> 3, (3 * 256 + tid) >> 3 };
    const int lkq = tid & 7;

    float acc[2][8][4];
#pragma unroll
    for (int mi = 0; mi < 2; mi++)
#pragma unroll
        for (int ni = 0; ni < 8; ni++)
#pragma unroll
            for (int e = 0; e < 4; e++) acc[mi][ni][e] = 0.f;

#define S_COPY(cidx)                                                           \
    do {                                                                       \
        const int s_ = (cidx) % STAGES;                                        \
        const int k0_ = (cidx) << 6;                                           \
        const int kb_ = (kBase + k0_) & kbMask;                                \
        const uint32_t sa_ = sb + (uint32_t)s_ * STAGE_T;                      \
        const uint32_t sb_ = sa_ + STAGE_B;                                    \
        _Pragma("unroll")                                                      \
        for (int i = 0; i < 4; i++) {                                          \
            const uint32_t off = ((uint32_t)lrow[i] * STRIDE + lkq * 8) * 2;   \
            const __half* ga =                                                 \
                Ab + (size_t)lrow[i] * lda + k0_ + lkq * 8;                    \
            asm volatile("cp.async.cg.shared.global [%0], [%1], 16;"           \
                         :: "r"(sa_ + off), "l"(ga));                          \
            const int rbr = bCol + lrow[i];                                    \
            const __half* gb =                                                 \
                Bt + (size_t)(rbr < N ? rbr : N - 1) * ldb + kb_ + lkq * 8;    \
            const uint32_t bsz = (rbr < N) ? 16u : 0u;                         \
            asm volatile("cp.async.cg.shared.global [%0], [%1], 16, %2;"       \
                         :: "r"(sb_ + off), "l"(gb), "r"(bsz));                \
        }                                                                      \
    } while (0)

    const int nchunk = kLen >> 6;
    int cread = 0;
#pragma unroll
    for (int i = 0; i < STAGES - 1; i++) {
        if (cread < nchunk) { S_COPY(cread); cread++; }
        asm volatile("cp.async.commit_group;" ::: "memory");
    }

    const uint32_t aRow = (uint32_t)(wr * 32 + (lane & 7) + ((lane >> 3) & 1) * 8);
    const uint32_t aKof = (uint32_t)((lane >> 4) * 8);
    const uint32_t bRowL = (uint32_t)(wc * 64 + (lane & 7) + ((lane >> 4) << 3));
    const uint32_t bKof = (uint32_t)(((lane >> 3) & 1) * 8);

    for (int c = 0; c < nchunk; c++) {
        asm volatile("cp.async.wait_group %0;" :: "n"(STAGES - 2) : "memory");
        __syncthreads();

        if (cread < nchunk) { S_COPY(cread); cread++; }
        asm volatile("cp.async.commit_group;" ::: "memory");

        const int s = c % STAGES;
        const uint32_t sAs = sb + (uint32_t)s * STAGE_T;
        const uint32_t sBs = sAs + STAGE_B;

#pragma unroll
        for (int ks = 0; ks < 4; ks++) {
            uint32_t afr[2][4];
#pragma unroll
            for (int mi = 0; mi < 2; mi++) {
                uint32_t ad = sAs + ((aRow + mi * 16) * STRIDE + ks * 16 + aKof) * 2;
                ldsm_x4(ad, afr[mi][0], afr[mi][1], afr[mi][2], afr[mi][3]);
            }
            uint32_t bfr[8][2];
#pragma unroll
            for (int nq = 0; nq < 4; nq++) {
                uint32_t bd = sBs + ((bRowL + nq * 16) * STRIDE + ks * 16 + bKof) * 2;
                uint32_t r0, r1, r2, r3;
                ldsm_x4(bd, r0, r1, r2, r3);
                bfr[nq * 2][0] = r0; bfr[nq * 2][1] = r1;
                bfr[nq * 2 + 1][0] = r2; bfr[nq * 2 + 1][1] = r3;
            }
#pragma unroll
            for (int mi = 0; mi < 2; mi++)
#pragma unroll
                for (int ni = 0; ni < 8; ni++)
                    mma16816(acc[mi][ni], afr[mi], bfr[ni][0], bfr[ni][1]);
        }
    }

    // epilogue (mode 1: fast softplus)
    float* Cz = C + (size_t)blockIdx.z * zStride;
#pragma unroll
    for (int mi = 0; mi < 2; mi++) {
#pragma unroll
        for (int ni = 0; ni < 8; ni++) {
            const int col = bCol + wc * 64 + ni * 8 + (lane & 3) * 2;
            if (col >= N) continue;
            const int r0 = bRow + wr * 32 + mi * 16 + (lane >> 2);
            float v0 = acc[mi][ni][0], v1 = acc[mi][ni][1];
            float v2 = acc[mi][ni][2], v3 = acc[mi][ni][3];
            if (mode == 1) {
                float b0 = bias[col], b1 = bias[col + 1];
                v0 += b0; v1 += b1; v2 += b0; v3 += b1;
                v0 = (v0 > 15.f) ? v0 : __logf(1.f + __expf(v0));
                v1 = (v1 > 15.f) ? v1 : __logf(1.f + __expf(v1));
                v2 = (v2 > 15.f) ? v2 : __logf(1.f + __expf(v2));
                v3 = (v3 > 15.f) ? v3 : __logf(1.f + __expf(v3));
            }
            *(float2*)&Cz[(size_t)r0 * ldc + col] = make_float2(v0, v1);
            *(float2*)&Cz[(size_t)(r0 + 8) * ldc + col] = make_float2(v2, v3);
        }
    }
}

// reduce split-K partials of proj; also emit dtin fp16 split for cols < 64
__global__ void reduce_proj(__half* __restrict__ dtin)
{
    int i = blockIdx.x * 256 + threadIdx.x;
    if (i >= ROWS * PROJ_N) return;
    float s = 0.f;
#pragma unroll
    for (int p = 0; p < KSPLIT; p++) s += g_projp[(size_t)p * ROWS * PROJ_N + i];
    g_proj[i] = s;
    int m = i / PROJ_N, col = i - m * PROJ_N;
    if (col < DT_RANK) {
        __half h = __float2half(s);
        __half l = __float2half(s - __half2float(h));
        size_t base = (size_t)m * (2 * DT_RANK);
        dtin[base + col] = h;
        dtin[base + DT_RANK + col] = l;
    }
}

// ---------------- conversion kernels ----------------
__global__ void rsplit(const float* __restrict__ in, int ldin, int M, int K,
                       __half* __restrict__ out)
{
    int i = blockIdx.x * 256 + threadIdx.x;
    if (i >= M * K) return;
    int m = i / K, k = i - m * K;
    float v = in[(size_t)m * ldin + k];
    __half h = __float2half(v);
    __half l = __float2half(v - __half2float(h));
    size_t base = (size_t)m * (2 * K);
    out[base + k] = h;
    out[base + K + k] = l;
}

__global__ void tsplit(const float* __restrict__ in, int K, int N,
                       __half* __restrict__ out)
{
    __shared__ float t[32][33];
    int k0 = blockIdx.y * 32, n0 = blockIdx.x * 32;
    int k = k0 + threadIdx.y, n = n0 + threadIdx.x;
    t[threadIdx.y][threadIdx.x] = (k < K && n < N) ? in[(size_t)k * N + n] : 0.f;
    __syncthreads();
    int on = n0 + threadIdx.y, ok = k0 + threadIdx.x;
    if (on < N && ok < K)
        out[(size_t)on * K + ok] = __float2half(t[threadIdx.x][threadIdx.y]);
}

// ---------------- conv + silu: sliding-window, 64 t-steps per thread -------
#define CONV_TT 64
__global__ void __launch_bounds__(256) conv_kernel(
    const float* __restrict__ conv_state,
    const float* __restrict__ conv_w,
    const float* __restrict__ conv_b)
{
    const int d = blockIdx.x * 256 + threadIdx.x;
    const int t0 = blockIdx.y * CONV_TT;
    const int b = blockIdx.z;

    const float w0 = conv_w[d * D_CONV + 0];
    const float w1 = conv_w[d * D_CONV + 1];
    const float w2 = conv_w[d * D_CONV + 2];
    const float w3 = conv_w[d * D_CONV + 3];
    const float cb = conv_b[d];

    const float* xin = g_xz + (size_t)b * T_LEN * (2 * D_INNER) + d;

    float v0, v1, v2;
    if (t0 == 0) {
        v0 = conv_state[((size_t)b * D_INNER + d) * (D_CONV - 1) + 0];
        v1 = conv_state[((size_t)b * D_INNER + d) * (D_CONV - 1) + 1];
        v2 = conv_state[((size_t)b * D_INNER + d) * (D_CONV - 1) + 2];
    } else {
        v0 = xin[(size_t)(t0 - 3) * (2 * D_INNER)];
        v1 = xin[(size_t)(t0 - 2) * (2 * D_INNER)];
        v2 = xin[(size_t)(t0 - 1) * (2 * D_INNER)];
    }

    float* xcv = g_xconv + (size_t)b * T_LEN * D_INNER + d;
    __half* xcs = g_xcs + (size_t)b * T_LEN * (2 * D_INNER) + d;

#pragma unroll 4
    for (int i = 0; i < CONV_TT; i++) {
        const int t = t0 + i;
        const float xn = xin[(size_t)t * (2 * D_INNER)];
        float acc = cb;
        acc = fmaf(w0, v0, acc);
        acc = fmaf(w1, v1, acc);
        acc = fmaf(w2, v2, acc);
        acc = fmaf(w3, xn, acc);
        const float sig = 1.f / (1.f + __expf(-acc));
        const float r = acc * sig;
        xcv[(size_t)t * D_INNER] = r;
        const __half h = __float2half(r);
        const __half l = __float2half(r - __half2float(h));
        const size_t base = (size_t)t * (2 * D_INNER);
        xcs[base] = h;
        xcs[base + D_INNER] = l;
        v0 = v1; v1 = v2; v2 = xn;
    }
}

__global__ void convstate_kernel(float* __restrict__ outp)
{
    int idx = blockIdx.x * 256 + threadIdx.x;
    if (idx >= B_SZ * D_INNER * (D_CONV - 1)) return;
    int j = idx % (D_CONV - 1);
    int d = (idx / (D_CONV - 1)) % D_INNER;
    int b = idx / (D_INNER * (D_CONV - 1));
    outp[idx] = g_xz[((size_t)b * T_LEN + (T_LEN - (D_CONV - 1) + j)) * (2 * D_INNER) + d];
}

// ---------------- selective scan: 4 threads per (b,d), deep prefetch -------
#define SCAN_PF 8
__global__ void __launch_bounds__(128) scan4(const float* __restrict__ ssm0,
                                             const float* __restrict__ A_log,
                                             const float* __restrict__ D_skip,
                                             float* __restrict__ h_out)
{
    int idx = blockIdx.x * 128 + threadIdx.x;   // 0..16383
    int s = idx & 3;
    int d = (idx >> 2) & (D_INNER - 1);
    int b = idx >> 13;
    int n0 = 4 * s;

    float4 hv = *(const float4*)&ssm0[((size_t)b * D_INNER + d) * D_STATE + n0];
    float4 al = *(const float4*)&A_log[d * D_STATE + n0];
    float A0 = -__expf(al.x), A1 = -__expf(al.y);
    float A2 = -__expf(al.z), A3 = -__expf(al.w);
    float dsk = D_skip[d];

    const float* dt_p = g_dt    + (size_t)b * T_LEN * D_INNER + d;
    const float* xc_p = g_xconv + (size_t)b * T_LEN * D_INNER + d;
    const float* z_p  = g_xz    + (size_t)b * T_LEN * (2 * D_INNER) + D_INNER + d;
    const float* bc_p = g_proj  + (size_t)b * T_LEN * PROJ_N + DT_RANK + n0;
    __half* ys = g_ys + (size_t)b * T_LEN * (2 * D_INNER) + d;

    float dt_b[SCAN_PF], xc_b[SCAN_PF], z_b[SCAN_PF];
    float4 B_b[SCAN_PF], C_b[SCAN_PF];
#pragma unroll
    for (int p = 0; p < SCAN_PF; p++) {
        dt_b[p] = dt_p[(size_t)p * D_INNER];
        xc_b[p] = xc_p[(size_t)p * D_INNER];
        z_b[p]  = z_p[(size_t)p * 2 * D_INNER];
        B_b[p]  = *(const float4*)(bc_p + (size_t)p * PROJ_N);
        C_b[p]  = *(const float4*)(bc_p + (size_t)p * PROJ_N + D_STATE);
    }

#pragma unroll 8
    for (int t = 0; t < T_LEN; t++) {
        const int cur = t & (SCAN_PF - 1);
        float dt = dt_b[cur], xc = xc_b[cur], z = z_b[cur];
        float4 Bv = B_b[cur], Cv = C_b[cur];
        if (t + SCAN_PF < T_LEN) {
            size_t o = (size_t)(t + SCAN_PF);
            dt_b[cur] = dt_p[o * D_INNER];
            xc_b[cur] = xc_p[o * D_INNER];
            z_b[cur]  = z_p[o * 2 * D_INNER];
            B_b[cur]  = *(const float4*)(bc_p + o * PROJ_N);
            C_b[cur]  = *(const float4*)(bc_p + o * PROJ_N + D_STATE);
        }
        float e0 = __expf(dt * A0);
        float e1 = __expf(dt * A1);
        float e2 = __expf(dt * A2);
        float e3 = __expf(dt * A3);
        float dx = dt * xc;
        hv.x = fmaf(e0, hv.x, dx * Bv.x);
        hv.y = fmaf(e1, hv.y, dx * Bv.y);
        hv.z = fmaf(e2, hv.z, dx * Bv.z);
        hv.w = fmaf(e3, hv.w, dx * Bv.w);
        float r = hv.x * Cv.x;
        r = fmaf(hv.y, Cv.y, r);
        r = fmaf(hv.z, Cv.z, r);
        r = fmaf(hv.w, Cv.w, r);
        r += __shfl_xor_sync(0xffffffffu, r, 1, 4);
        r += __shfl_xor_sync(0xffffffffu, r, 2, 4);
        if (s == 0) {
            float yv = fmaf(dsk, xc, r);
            float sz = z / (1.f + __expf(-z));
            yv *= sz;
            __half h = __float2half(yv);
            __half l = __float2half(yv - __half2float(h));
            size_t base = (size_t)t * (2 * D_INNER);
            ys[base] = h;
            ys[base + D_INNER] = l;
        }
    }
    *(float4*)&h_out[((size_t)b * D_INNER + d) * D_STATE + n0] = hv;
}

// ----------------------------------------------------------------------------
extern "C" void kernel_launch(void* const* d_in, const int* in_sizes, int n_in,
                              void* d_out, int out_size)
{
    const float* x          = (const float*)d_in[0];
    const float* ssm_state  = (const float*)d_in[1];
    const float* conv_state = (const float*)d_in[2];
    const float* w_in       = (const float*)d_in[3];
    const float* conv_w     = (const float*)d_in[4];
    const float* conv_b     = (const float*)d_in[5];
    const float* w_x        = (const float*)d_in[6];
    const float* w_dt       = (const float*)d_in[7];
    const float* b_dt       = (const float*)d_in[8];
    const float* A_log      = (const float*)d_in[9];
    const float* D_skip     = (const float*)d_in[10];
    const float* w_out      = (const float*)d_in[11];
    float* out = (float*)d_out;

    cudaStreamCaptureStatus cs = cudaStreamCaptureStatusNone;
    cudaStreamIsCapturing(cudaStreamLegacy, &cs);
    if (cs == cudaStreamCaptureStatusNone)
        cudaFuncSetAttribute(gemm_mma, cudaFuncAttributeMaxDynamicSharedMemorySize, GEMM_SMEM);

    float *xz, *proj, *projp, *dt;
    __half *xs, *wint, *xcs, *wxt, *dtin, *wdtt, *ys, *wott;
    cudaGetSymbolAddress((void**)&xz,    g_xz);
    cudaGetSymbolAddress((void**)&proj,  g_proj);
    cudaGetSymbolAddress((void**)&projp, g_projp);
    cudaGetSymbolAddress((void**)&dt,    g_dt);
    cudaGetSymbolAddress((void**)&xs,    g_xs);
    cudaGetSymbolAddress((void**)&wint,  g_wint);
    cudaGetSymbolAddress((void**)&xcs,   g_xcs);
    cudaGetSymbolAddress((void**)&wxt,   g_wxt);
    cudaGetSymbolAddress((void**)&dtin,  g_dtin);
    cudaGetSymbolAddress((void**)&wdtt,  g_wdtt);
    cudaGetSymbolAddress((void**)&ys,    g_ys);
    cudaGetSymbolAddress((void**)&wott,  g_wott);

    // Launch order keeps gemm1 as the 4th launch (ncu capture slot).
    rsplit<<<(ROWS * DIM + 255) / 256, 256>>>(x, DIM, ROWS, DIM, xs);                   // 1
    tsplit<<<dim3((2 * D_INNER) / 32, DIM / 32), dim3(32, 32)>>>(w_in, DIM, 2 * D_INNER, wint); // 2
    tsplit<<<dim3(DIM / 32, D_INNER / 32), dim3(32, 32)>>>(w_out, D_INNER, DIM, wott);          // 3

    // 4) xz = x @ w_in   (Kp = 2048, B period 1024)  <-- profiled launch
    gemm_mma<<<dim3(32, 32, 1), 256, GEMM_SMEM>>>(
        xs, 2 * DIM, wint, DIM, DIM - 1, 2 * D_INNER,
        xz, 2 * D_INNER, 2 * DIM, 0, nullptr, 0);

    // 5) depthwise conv + silu
    conv_kernel<<<dim3(D_INNER / 256, T_LEN / CONV_TT, B_SZ), 256>>>(conv_state, conv_w, conv_b);
    // 6) new conv state
    convstate_kernel<<<(B_SZ * D_INNER * (D_CONV - 1) + 255) / 256, 256>>>(out + OFF_CONV);
    // 7)
    tsplit<<<dim3(3, D_INNER / 32), dim3(32, 32)>>>(w_x, D_INNER, PROJ_N, wxt);

    // 8) proj = x_conv @ w_x  (Kp = 4096, B period 2048, split-K=4)
    gemm_mma<<<dim3(1, 32, KSPLIT), 256, GEMM_SMEM>>>(
        xcs, 2 * D_INNER, wxt, D_INNER, D_INNER - 1, PROJ_N,
        projp, PROJ_N, (2 * D_INNER) / KSPLIT, (size_t)ROWS * PROJ_N, nullptr, 0);
    // 9) reduce + emit dtin
    reduce_proj<<<(ROWS * PROJ_N + 255) / 256, 256>>>(dtin);
    // 10)
    tsplit<<<dim3(D_INNER / 32, 2), dim3(32, 32)>>>(w_dt, DT_RANK, D_INNER, wdtt);

    // 11) dt = softplus(proj[:, :64] @ w_dt + b_dt)  (Kp = 128, B period 64)
    gemm_mma<<<dim3(16, 32, 1), 256, GEMM_SMEM>>>(
        dtin, 2 * DT_RANK, wdtt, DT_RANK, DT_RANK - 1, D_INNER,
        dt, D_INNER, 2 * DT_RANK, 0, b_dt, 1);

    // 12) selective scan (8-deep register prefetch)
    scan4<<<(B_SZ * D_INNER * 4) / 128, 128>>>(ssm_state, A_log, D_skip, out + OFF_H);

    // 13) out = y_gated @ w_out  (Kp = 4096, B period 2048)
    gemm_mma<<<dim3(8, 32, 1), 256, GEMM_SMEM>>>(
        ys, 2 * D_INNER, wott, D_INNER, D_INNER - 1, DIM,
        out, DIM, 2 * D_INNER, 0, nullptr, 0);
}